// round 4
// baseline (speedup 1.0000x reference)
#include <cuda_runtime.h>
#include <cuda_bf16.h>
#include <cstdint>

#define B_    16
#define N_    1024
#define TIN_  24
#define TO_   20
#define CIN_  32
#define C_    64
#define NT_   (N_*TO_)          // 20480

#if defined(__CUDA_ARCH_FEAT_SM103_ALL) || defined(__CUDA_ARCH_FEAT_SM100_ALL)
#define TC_PATH 1
#endif

// ---------------- scratch (device globals; no allocs) ----------------
__device__ float g_tem20[B_*CIN_*NT_];
__device__ float g_y    [B_*C_*NT_];
__device__ float g_qkv  [B_*192*NT_];    // qkv, later reused for [u|h0f|h1f]
__device__ float g_att  [B_*C_*NT_];
__device__ float g_cat0 [B_*192*NT_];
__device__ float g_cat1 [B_*192*NT_];
__device__ float g_h01  [B_*128*NT_];
__device__ float g_wqkv [192*96];
__device__ float g_bqkv [192];
__device__ float g_w3   [192*128];
__device__ float g_b3   [192];
__device__ __align__(256) __nv_bfloat16 g_Ah [4*1024*1024];
__device__ __align__(256) __nv_bfloat16 g_Al [4*1024*1024];
__device__ __align__(256) __nv_bfloat16 g_xth[20480*1024];   // [j][k=n]
__device__ __align__(256) __nv_bfloat16 g_xtl[20480*1024];

// ======================= PTX helpers =======================
__device__ __forceinline__ uint32_t smem_u32(const void* p) {
    uint32_t a;
    asm("{ .reg .u64 t; cvta.to.shared.u64 t, %1; cvt.u32.u64 %0, t; }" : "=r"(a) : "l"(p));
    return a;
}
__device__ __forceinline__ void cpa16(uint32_t dst, const void* src) {
    asm volatile("cp.async.cg.shared.global [%0], [%1], 16;" :: "r"(dst), "l"(src));
}
__device__ __forceinline__ void cpa_commit() { asm volatile("cp.async.commit_group;" ::: "memory"); }
__device__ __forceinline__ void cpa_wait1()  { asm volatile("cp.async.wait_group 1;" ::: "memory"); }
__device__ __forceinline__ void cpa_wait0()  { asm volatile("cp.async.wait_group 0;" ::: "memory"); }
#define SWZ(o) ((o) ^ (((o) >> 3) & 0x70))

#ifdef TC_PATH
__device__ __forceinline__ uint32_t elect1() {
    uint32_t p;
    asm volatile("{\n\t.reg .pred p;\n\telect.sync _|p, 0xFFFFFFFF;\n\tselp.b32 %0, 1, 0, p;\n\t}" : "=r"(p));
    return p;
}
#define MBARRIER_INIT(addr, cnt) \
    asm volatile("mbarrier.init.shared.b64 [%0], %1;" :: "r"(addr), "r"(cnt) : "memory")
#define MBARRIER_INVAL(addr) \
    asm volatile("mbarrier.inval.shared.b64 [%0];" :: "r"(addr) : "memory")
#define MBARRIER_WAIT_PARITY(mbar_smem_addr, phase_parity) do { \
    uint32_t _mbar = (uint32_t)(mbar_smem_addr); \
    uint32_t _parity = (uint32_t)(phase_parity); \
    uint32_t _done; \
    asm volatile("{\n\t.reg .pred p;\n\t" \
        "mbarrier.try_wait.parity.acquire.cta.shared::cta.b64 p, [%1], %2;\n\t" \
        "selp.b32 %0, 1, 0, p;\n\t}" : "=r"(_done) : "r"(_mbar), "r"(_parity) : "memory"); \
    if (!_done) { \
        asm volatile("{\n\t.reg .pred P1;\n\t" \
            "WAIT_LOOP_%=:\n\t" \
            "mbarrier.try_wait.parity.acquire.cta.shared::cta.b64 P1, [%0], %1, 0x989680;\n\t" \
            "@P1 bra.uni WAIT_DONE_%=;\n\t" \
            "bra.uni WAIT_LOOP_%=;\n\t" \
            "WAIT_DONE_%=:\n\t}" :: "r"(_mbar), "r"(_parity) : "memory"); \
    } \
} while(0)
#define TCGEN05_ALLOC(saddr, n) \
    asm volatile("tcgen05.alloc.cta_group::1.sync.aligned.shared::cta.b32 [%0], %1;" \
        :: "r"((uint32_t)(saddr)), "r"((uint32_t)(n)) : "memory")
#define TCGEN05_DEALLOC(tmem, n) \
    asm volatile("tcgen05.dealloc.cta_group::1.sync.aligned.b32 %0, %1;" :: "r"(tmem), "r"((uint32_t)(n)))
#define TCGEN05_RELINQ() \
    asm volatile("tcgen05.relinquish_alloc_permit.cta_group::1.sync.aligned;")
#define TCGEN05_COMMIT(mbar) \
    asm volatile("tcgen05.commit.cta_group::1.mbarrier::arrive::one.shared::cluster.b64 [%0];" \
        :: "r"((uint32_t)(mbar)) : "memory")
#define TCGEN05_FENCE_AFTER() asm volatile("tcgen05.fence::after_thread_sync;" ::: "memory")
#define TCGEN05_WAIT_LD() asm volatile("tcgen05.wait::ld.sync.aligned;" ::: "memory")
#define TCGEN05_LD_32X32B_X32(r, tmem_addr) \
    asm volatile("tcgen05.ld.sync.aligned.32x32b.x32.b32 " \
        "{%0, %1, %2, %3, %4, %5, %6, %7, %8, %9, %10, %11, %12, %13, %14, %15, " \
        " %16, %17, %18, %19, %20, %21, %22, %23, %24, %25, %26, %27, %28, %29, %30, %31}, [%32];" \
        : "=r"((r)[0]),  "=r"((r)[1]),  "=r"((r)[2]),  "=r"((r)[3]), \
          "=r"((r)[4]),  "=r"((r)[5]),  "=r"((r)[6]),  "=r"((r)[7]), \
          "=r"((r)[8]),  "=r"((r)[9]),  "=r"((r)[10]), "=r"((r)[11]), \
          "=r"((r)[12]), "=r"((r)[13]), "=r"((r)[14]), "=r"((r)[15]), \
          "=r"((r)[16]), "=r"((r)[17]), "=r"((r)[18]), "=r"((r)[19]), \
          "=r"((r)[20]), "=r"((r)[21]), "=r"((r)[22]), "=r"((r)[23]), \
          "=r"((r)[24]), "=r"((r)[25]), "=r"((r)[26]), "=r"((r)[27]), \
          "=r"((r)[28]), "=r"((r)[29]), "=r"((r)[30]), "=r"((r)[31]) \
        : "r"(tmem_addr))

__device__ __forceinline__ uint64_t make_desc(uint32_t addr) {
    return 0x4000404000010000ULL | (uint64_t)((addr >> 4) & 0x3FFF);
}
__device__ __forceinline__ void mma_f16_ss_cg1(uint32_t d, uint64_t a, uint64_t b,
                                               uint32_t idesc, bool acc) {
    uint32_t en = acc ? 1u : 0u;
    asm volatile("{\n\t.reg .pred p;\n\tsetp.ne.u32 p, %5, 0;\n\t"
        "tcgen05.mma.cta_group::1.kind::f16 [%0], %1, %2, %3, {%4, %4, %4, %4}, p;\n\t}"
        :: "r"(d), "l"(a), "l"(b), "r"(idesc), "r"(0u), "r"(en) : "memory");
}
// idesc: dtype F32, atype BF16, btype BF16, N=256, M=128
#define IDESC_NC 0x8400490u
#endif // TC_PATH

// ---------------- tem slice ----------------
__global__ void k_slice_tem(const float* __restrict__ tem) {
    int i = blockIdx.x * 256 + threadIdx.x;
    int t = i % TO_;
    int rest = i / TO_;
    g_tem20[i] = tem[rest * TIN_ + t + 4];
}

// ---------------- dilated temporal conv + relu ----------------
#define NPB 4
__global__ __launch_bounds__(256) void k_tc(const float* __restrict__ x,
                                            const float* __restrict__ w,
                                            const float* __restrict__ bias) {
    __shared__ float xs[NPB][CIN_][TIN_];
    __shared__ float ws_t[96*65];
    __shared__ float bs[C_];
    int tid = threadIdx.x;
    int blk = blockIdx.x;
    int b  = blk / (N_/NPB);
    int n0 = (blk % (N_/NPB)) * NPB;

    for (int i = tid; i < C_*CIN_*3; i += 256) {
        int o = i / 96, k = i % 96;
        ws_t[k*65 + o] = w[i];
    }
    if (tid < C_) bs[tid] = bias[tid];
    for (int i = tid; i < NPB*CIN_*TIN_; i += 256) {
        int nn = i / (CIN_*TIN_);
        int r  = i % (CIN_*TIN_);
        int ci = r / TIN_, tt = r % TIN_;
        xs[nn][ci][tt] = x[((b*CIN_ + ci)*N_ + n0 + nn)*TIN_ + tt];
    }
    __syncthreads();

    int co = tid & 63, nn = tid >> 6;
    float acc[TO_];
#pragma unroll
    for (int t = 0; t < TO_; t++) acc[t] = bs[co];
    for (int ci = 0; ci < CIN_; ci++) {
        float w0 = ws_t[(ci*3 + 0)*65 + co];
        float w1 = ws_t[(ci*3 + 1)*65 + co];
        float w2 = ws_t[(ci*3 + 2)*65 + co];
        const float* xr = xs[nn][ci];
#pragma unroll
        for (int t = 0; t < TO_; t++)
            acc[t] += w0*xr[t] + w1*xr[t+2] + w2*xr[t+4];
    }
    int ob = ((b*C_ + co)*N_ + n0 + nn)*TO_;
#pragma unroll
    for (int t = 0; t < TO_; t++) g_y[ob + t] = fmaxf(acc[t], 0.f);
}

// ---------------- weight packing ----------------
__global__ void k_pack_qkv(const float* __restrict__ wq, const float* __restrict__ bq,
                           const float* __restrict__ wk, const float* __restrict__ bk,
                           const float* __restrict__ wv, const float* __restrict__ bv) {
    int i = blockIdx.x * 256 + threadIdx.x;
    if (i < 3*64*96) {
        int s = i / 6144, r = i % 6144;
        g_wqkv[i] = (s == 0 ? wq : s == 1 ? wk : wv)[r];
    }
    if (i < 192) {
        int s = i >> 6, r = i & 63;
        g_bqkv[i] = (s == 0 ? bq : s == 1 ? bk : bv)[r];
    }
}
__global__ void k_pack_w3(const float* __restrict__ wadp, const float* __restrict__ badp,
                          const float* __restrict__ w0f) {
    int i = blockIdx.x * 256 + threadIdx.x;
    if (i < 192*128) {
        int row = i >> 7, col = i & 127;
        float v;
        if (row < 64)        v = wadp[i];
        else if (row < 128)  v = (col < 64)  ? w0f[(row-64)*64 + col]       : 0.f;
        else                 v = (col >= 64) ? w0f[(row-128)*64 + col - 64] : 0.f;
        g_w3[i] = v;
    }
    if (i < 192) g_b3[i] = (i < 64) ? badp[i] : 0.f;
}

// ---------------- generic batched conv1x1 GEMM ----------------
__global__ __launch_bounds__(256) void k_conv1x1(
    const float* __restrict__ W, const float* __restrict__ bias,
    const float* __restrict__ X0, int bs0,
    const float* __restrict__ X1, int bs1, int ksplit,
    int K, float* __restrict__ out, int outC, int chOff, int doRelu)
{
    __shared__ float Ws[16][65];
    __shared__ float Xs[16][132];
    int tid = threadIdx.x;
    int b   = blockIdx.z;
    int j0  = blockIdx.x * 128;
    int yb  = blockIdx.y;
    W += yb * 64 * K;
    if (bias) bias += yb * 64;
    chOff += yb * 64;
    int ty  = tid >> 4, tx = tid & 15;

    float acc[4][8];
#pragma unroll
    for (int i = 0; i < 4; i++)
#pragma unroll
        for (int j = 0; j < 8; j++) acc[i][j] = 0.f;

    int wm = tid >> 2, wk4 = (tid & 3) * 4;
    int xr0 = tid >> 5, xc = (tid & 31) * 4;

    for (int k0 = 0; k0 < K; k0 += 16) {
        __syncthreads();
        float4 w4 = *(const float4*)(&W[wm*K + k0 + wk4]);
        Ws[wk4+0][wm] = w4.x; Ws[wk4+1][wm] = w4.y;
        Ws[wk4+2][wm] = w4.z; Ws[wk4+3][wm] = w4.w;
#pragma unroll
        for (int rr = 0; rr < 2; rr++) {
            int r = xr0 + rr*8;
            int k = k0 + r;
            const float* src = (k < ksplit) ? (X0 + (size_t)bs0*b + (size_t)k*NT_)
                                            : (X1 + (size_t)bs1*b + (size_t)(k - ksplit)*NT_);
            *(float4*)(&Xs[r][xc]) = *(const float4*)(src + j0 + xc);
        }
        __syncthreads();
#pragma unroll
        for (int kk = 0; kk < 16; kk++) {
            float a[4], xv[8];
#pragma unroll
            for (int i = 0; i < 4; i++) a[i] = Ws[kk][ty*4 + i];
#pragma unroll
            for (int j = 0; j < 8; j++) xv[j] = Xs[kk][tx*8 + j];
#pragma unroll
            for (int i = 0; i < 4; i++)
#pragma unroll
                for (int j = 0; j < 8; j++) acc[i][j] += a[i]*xv[j];
        }
    }
#pragma unroll
    for (int i = 0; i < 4; i++) {
        int m = ty*4 + i;
        float bv = bias ? bias[m] : 0.f;
        size_t obase = ((size_t)b*outC + chOff + m)*NT_ + j0 + tx*8;
#pragma unroll
        for (int j = 0; j < 8; j++) {
            float v = acc[i][j] + bv;
            if (doRelu) v = fmaxf(v, 0.f);
            out[obase + j] = v;
        }
    }
}

// ---------------- fused masked MHA ----------------
__global__ __launch_bounds__(256) void k_attn() {
    __shared__ float sbuf[8][880];
    int warp = threadIdx.x >> 5, lane = threadIdx.x & 31;
    int g = blockIdx.x * 8 + warp;
    int b = g >> 13;
    int h = (g >> 10) & 7;
    int n = g & 1023;
    float* q = sbuf[warp];
    float* k = q + 160;
    float* v = k + 160;
    float* S = v + 160;

    size_t base = (size_t)(b*192)*NT_ + n*TO_;
    for (int idx = lane; idx < 160; idx += 32) {
        int d = idx / TO_, t = idx % TO_;
        size_t co = (size_t)(h*8 + d)*NT_ + t;
        q[idx] = g_qkv[base + co];
        k[idx] = g_qkv[base + (size_t)64*NT_ + co];
        v[idx] = g_qkv[base + (size_t)128*NT_ + co];
    }
    __syncwarp();
    for (int idx = lane; idx < 400; idx += 32) {
        int t = idx / TO_, s = idx % TO_;
        if (s <= t) {
            float acc = 0.f;
#pragma unroll
            for (int d = 0; d < 8; d++) acc += q[d*TO_ + t] * k[d*TO_ + s];
            S[idx] = acc * 0.35355339059327373f;
        }
    }
    __syncwarp();
    if (lane < TO_) {
        int t = lane;
        float mx = -1e30f;
        for (int s = 0; s <= t; s++) mx = fmaxf(mx, S[t*TO_ + s]);
        float sum = 0.f;
        for (int s = 0; s <= t; s++) { float e = __expf(S[t*TO_ + s] - mx); S[t*TO_ + s] = e; sum += e; }
        float inv = 1.f / sum;
        for (int s = 0; s <= t; s++) S[t*TO_ + s] *= inv;
    }
    __syncwarp();
    size_t obase = (size_t)(b*C_)*NT_ + n*TO_;
    for (int idx = lane; idx < 160; idx += 32) {
        int d = idx / TO_, t = idx % TO_;
        float acc = 0.f;
        for (int s = 0; s <= t; s++) acc += S[t*TO_ + s] * v[d*TO_ + s];
        g_att[obase + (size_t)(h*8 + d)*NT_ + t] = acc;
    }
}

// ---------------- split A into bf16 hi/lo ----------------
__global__ void k_split_A(const float* __restrict__ A0, const float* __restrict__ A1,
                          const float* __restrict__ A2, const float* __restrict__ A3) {
    int i = blockIdx.x * 256 + threadIdx.x;         // 4*1024*1024
    int z = i >> 20, r = i & 1048575;
    const float* A = (z == 0) ? A0 : (z == 1) ? A1 : (z == 2) ? A2 : A3;
    float v = A[r];
    __nv_bfloat16 h = __float2bfloat16(v);
    g_Ah[i] = h;
    g_Al[i] = __float2bfloat16(v - __bfloat162float(h));
}

// ---------------- split x2: cat0 ch0-63 -> cat1 copy + [j][k] bf16 hi/lo ----------------
__global__ void k_split_x() {
    int i = blockIdx.x * 256 + threadIdx.x;         // 20480*1024
    int j = i >> 10, n = i & 1023;
    int b = j / 1280, r = j % 1280, c = r / 20, t = r % 20;
    size_t src = (size_t)(b*192 + c)*NT_ + n*20 + t;
    float v = g_cat0[src];
    g_cat1[src] = v;
    __nv_bfloat16 h = __float2bfloat16(v);
    g_xth[i] = h;
    g_xtl[i] = __float2bfloat16(v - __bfloat162float(h));
}

// ---------------- tensor-core nconv ----------------
// D[128m x 256j] = sum_k A[m][k] * Xt[j][k], split-bf16 x3, K=1024 in 16 chunks of 64.
#define STAGE_BYTES 98304
#define SMEM_TOTAL  (1024 + 2*STAGE_BYTES)

__device__ __forceinline__ void load_chunk(int k0, uint32_t sbase,
                                           const __nv_bfloat16* Ah, const __nv_bfloat16* Al,
                                           int m0, int j0, int tid) {
    for (int g = tid; g < 6144; g += 256) {
        uint32_t dst; const void* src;
        if (g < 2048) {
            int part = g >> 10;
            int gg = g & 1023;
            int r = gg >> 3, c8 = gg & 7;
            const __nv_bfloat16* Ab = part ? Al : Ah;
            src = Ab + (size_t)(m0 + r)*1024 + k0 + c8*8;
            dst = sbase + part*16384 + SWZ(r*128 + c8*16);
        } else {
            int part = (g - 2048) >> 11;
            int gg = (g - 2048) & 2047;
            int r = gg >> 3, c8 = gg & 7;
            const __nv_bfloat16* Xb = part ? g_xtl : g_xth;
            src = Xb + (size_t)(j0 + r)*1024 + k0 + c8*8;
            dst = sbase + 32768 + part*32768 + SWZ(r*128 + c8*16);
        }
        cpa16(dst, src);
    }
}

__global__ __launch_bounds__(256) void k_nconv_tc() {
    extern __shared__ char smem[];
    int tid = threadIdx.x, wid = tid >> 5, lane = tid & 31;
    int j0 = blockIdx.x * 256, m0 = blockIdx.y * 128, z = blockIdx.z;
    const __nv_bfloat16* Ah = g_Ah + (size_t)z*1024*1024;
    const __nv_bfloat16* Al = g_Al + (size_t)z*1024*1024;
    float* Dt = (float*)(smem + 1024);          // [256 cols][129]

#ifdef TC_PATH
    uint32_t sb = smem_u32(smem);
    if (wid == 0) TCGEN05_ALLOC(sb, 256);
    if (tid == 0) { MBARRIER_INIT(sb+8, 1); MBARRIER_INIT(sb+16, 1); }
    __syncthreads();
    uint32_t tmem;
    asm volatile("ld.shared.b32 %0, [%1];" : "=r"(tmem) : "r"(sb));
    uint32_t buf_base = sb + 1024;

    // prologue: chunk 0 -> buf 0
    load_chunk(0, buf_base, Ah, Al, m0, j0, tid);
    cpa_commit();

    int ph0 = 0, ph1 = 0;
    for (int ch = 0; ch < 16; ch++) {
        int buf = ch & 1;
        if (ch + 1 < 16) {
            int nb = 1 - buf;
            if (ch >= 1) {
                MBARRIER_WAIT_PARITY(sb + 8 + 8*nb, (nb == 0) ? ph0 : ph1);
                if (nb == 0) ph0 ^= 1; else ph1 ^= 1;
            }
            load_chunk((ch+1)*64, buf_base + STAGE_BYTES*nb, Ah, Al, m0, j0, tid);
            cpa_commit();
            cpa_wait1();
        } else {
            cpa_wait0();
        }
        __syncthreads();
        if (wid == 0) {
            asm volatile("fence.proxy.async.shared::cta;" ::: "memory");
            if (elect1()) {
                uint32_t s0 = buf_base + STAGE_BYTES*buf;
                uint64_t ah = make_desc(s0);
                uint64_t al = make_desc(s0 + 16384);
                uint64_t xh = make_desc(s0 + 32768);
                uint64_t xl = make_desc(s0 + 65536);
#pragma unroll
                for (int ks = 0; ks < 4; ks++) {
                    mma_f16_ss_cg1(tmem, ah + 2*ks, xh + 2*ks, IDESC_NC, !(ch == 0 && ks == 0));
                    mma_f16_ss_cg1(tmem, ah + 2*ks, xl + 2*ks, IDESC_NC, true);
                    mma_f16_ss_cg1(tmem, al + 2*ks, xh + 2*ks, IDESC_NC, true);
                }
                TCGEN05_COMMIT(sb + 8 + 8*buf);
            }
        }
    }
    MBARRIER_WAIT_PARITY(sb + 16, ph1);
    TCGEN05_FENCE_AFTER();

    // TMEM -> SMEM (transposed, padded)
    {
        int sub = wid & 3, half = wid >> 2;
        int m = sub*32 + lane;
#pragma unroll
        for (int i = 0; i < 4; i++) {
            uint32_t r[32];
            int cb = half*128 + i*32;
            TCGEN05_LD_32X32B_X32(r, tmem + cb);
            TCGEN05_WAIT_LD();
#pragma unroll
            for (int c = 0; c < 32; c++) Dt[(cb + c)*129 + m] = __uint_as_float(r[c]);
        }
    }
    __syncthreads();
    if (tid == 0) { MBARRIER_INVAL(sb+8); MBARRIER_INVAL(sb+16); }
    if (wid == 0) { TCGEN05_RELINQ(); TCGEN05_DEALLOC(tmem, 256); }
    __syncthreads();
#else
    // ---- portable FFMA fallback (used only if the sm_103a cubin is absent) ----
    float* As = (float*)(smem + 1024 + 256*129*4);  // [8][132]
    float* Xs = As + 8*132;                         // [8][132]
    int ty = tid >> 4, tx = tid & 15;
    for (int jp = 0; jp < 2; jp++) {
        float acc[8][8];
#pragma unroll
        for (int i = 0; i < 8; i++)
#pragma unroll
            for (int j = 0; j < 8; j++) acc[i][j] = 0.f;
        for (int k0 = 0; k0 < 1024; k0 += 8) {
            __syncthreads();
            for (int idx = tid; idx < 2048; idx += 256) {
                int half = idx >> 10;
                int e = idx & 1023;
                int row = e >> 3, kk = e & 7;
                if (half == 0) {
                    size_t o = (size_t)(m0 + row)*1024 + k0 + kk;
                    As[kk*132 + row] = __bfloat162float(Ah[o]) + __bfloat162float(Al[o]);
                } else {
                    size_t o = (size_t)(j0 + jp*128 + row)*1024 + k0 + kk;
                    Xs[kk*132 + row] = __bfloat162float(g_xth[o]) + __bfloat162float(g_xtl[o]);
                }
            }
            __syncthreads();
#pragma unroll
            for (int kk = 0; kk < 8; kk++) {
                float a[8], xv[8];
#pragma unroll
                for (int i = 0; i < 8; i++) a[i] = As[kk*132 + ty*8 + i];
#pragma unroll
                for (int j = 0; j < 8; j++) xv[j] = Xs[kk*132 + tx*8 + j];
#pragma unroll
                for (int i = 0; i < 8; i++)
#pragma unroll
                    for (int j = 0; j < 8; j++) acc[i][j] += a[i]*xv[j];
            }
        }
        __syncthreads();
#pragma unroll
        for (int i = 0; i < 8; i++)
#pragma unroll
            for (int j = 0; j < 8; j++)
                Dt[(jp*128 + tx*8 + j)*129 + ty*8 + i] = acc[i][j];
    }
    __syncthreads();
#endif

    // common epilogue: Dt -> global scatter
    int c = tid;
    int j = j0 + c;
    int bc = j / TO_, t = j - bc*TO_;
    int bi = bc >> 6, ci = bc & 63;
    float* dest = (z < 2) ? g_cat0 : g_cat1;
    int chBase = (z & 1) ? 128 : 64;
    size_t obase = (size_t)(bi*192 + chBase + ci)*NT_ + (size_t)m0*TO_ + t;
#pragma unroll 4
    for (int mm = 0; mm < 128; mm++)
        dest[obase + (size_t)mm*TO_] = Dt[c*129 + mm];
}

// ---------------- micro fusion ----------------
__global__ void k_fusion(float* __restrict__ out) {
    int p = blockIdx.x * 256 + threadIdx.x;       // B*NT
    int b = p / NT_, j = p % NT_;
    size_t base = (size_t)b*192*NT_ + j;
    float s0 = 0.f, s1 = 0.f;
    for (int c = 0; c < C_; c++) {
        float uu = g_qkv[base + (size_t)c*NT_];
        s0 += g_qkv[base + (size_t)(64 + c)*NT_]  * uu;
        s1 += g_qkv[base + (size_t)(128 + c)*NT_] * uu;
    }
    float m  = fmaxf(s0, s1);
    float e0 = __expf(s0 - m), e1 = __expf(s1 - m);
    float inv = 1.f / (e0 + e1);
    float a0 = e0 * inv, a1 = e1 * inv;
    size_t ob = (size_t)b*C_*NT_ + j;
    for (int c = 0; c < C_; c++) {
        out[ob + (size_t)c*NT_] = a0 * g_qkv[base + (size_t)(64 + c)*NT_]
                                + a1 * g_qkv[base + (size_t)(128 + c)*NT_];
    }
}

// ---------------- launch ----------------
extern "C" void kernel_launch(void* const* d_in, const int* in_sizes, int n_in,
                              void* d_out, int out_size) {
    const float* x    = (const float*)d_in[0];
    const float* tem  = (const float*)d_in[1];
    const float* A0   = (const float*)d_in[2];
    const float* A1   = (const float*)d_in[3];
    const float* A2   = (const float*)d_in[4];
    const float* A3   = (const float*)d_in[5];
    const float* w_tc = (const float*)d_in[6];
    const float* b_tc = (const float*)d_in[7];
    const float* wq   = (const float*)d_in[8];
    const float* bq   = (const float*)d_in[9];
    const float* wk   = (const float*)d_in[10];
    const float* bk   = (const float*)d_in[11];
    const float* wv   = (const float*)d_in[12];
    const float* bv   = (const float*)d_in[13];
    const float* wo   = (const float*)d_in[14];
    const float* bo   = (const float*)d_in[15];
    const float* wg0  = (const float*)d_in[16];
    const float* bg0  = (const float*)d_in[17];
    const float* wg1  = (const float*)d_in[18];
    const float* bg1  = (const float*)d_in[19];
    const float* wadp = (const float*)d_in[20];
    const float* badp = (const float*)d_in[21];
    const float* w0f  = (const float*)d_in[22];
    float* out = (float*)d_out;

    float *p_tem20, *p_y, *p_qkv, *p_att, *p_cat0, *p_cat1, *p_h01, *p_wqkv, *p_bqkv, *p_w3, *p_b3;
    cudaGetSymbolAddress((void**)&p_tem20, g_tem20);
    cudaGetSymbolAddress((void**)&p_y,     g_y);
    cudaGetSymbolAddress((void**)&p_qkv,   g_qkv);
    cudaGetSymbolAddress((void**)&p_att,   g_att);
    cudaGetSymbolAddress((void**)&p_cat0,  g_cat0);
    cudaGetSymbolAddress((void**)&p_cat1,  g_cat1);
    cudaGetSymbolAddress((void**)&p_h01,   g_h01);
    cudaGetSymbolAddress((void**)&p_wqkv,  g_wqkv);
    cudaGetSymbolAddress((void**)&p_bqkv,  g_bqkv);
    cudaGetSymbolAddress((void**)&p_w3,    g_w3);
    cudaGetSymbolAddress((void**)&p_b3,    g_b3);

    cudaFuncSetAttribute(k_nconv_tc, cudaFuncAttributeMaxDynamicSharedMemorySize, SMEM_TOTAL);

    // prep
    k_slice_tem<<<(B_*CIN_*NT_)/256, 256>>>(tem);
    k_pack_qkv<<<72, 256>>>(wq, bq, wk, bk, wv, bv);
    k_pack_w3<<<96, 256>>>(wadp, badp, w0f);
    k_split_A<<<(4*1024*1024)/256, 256>>>(A0, A1, A2, A3);
    // temporal conv
    k_tc<<<B_*N_/NPB, 256>>>(x, w_tc, b_tc);
    // fused QKV
    k_conv1x1<<<dim3(160, 3, B_), 256>>>(p_wqkv, p_bqkv, p_y, C_*NT_, p_tem20, CIN_*NT_, 64, 96,
                                         p_qkv, 192, 0, 0);
    // attention
    k_attn<<<B_*8*N_/8, 256>>>();
    // WO + relu -> cat0 ch0-63
    k_conv1x1<<<dim3(160, 1, B_), 256>>>(wo, bo, p_att, C_*NT_, p_att, 0, 64, 64,
                                         p_cat0, 192, 0, 1);
    // split x2 into cat1 copy + bf16 hi/lo [j][k]
    k_split_x<<<(20480*1024)/256, 256>>>();
    // tensor-core graph diffusion
    k_nconv_tc<<<dim3(80, 8, 4), 256, SMEM_TOTAL>>>();
    // h0, h1 (K=192) + relu
    k_conv1x1<<<dim3(160, 1, B_), 256>>>(wg0, bg0, p_cat0, 192*NT_, p_cat0, 0, 192, 192,
                                         p_h01, 128, 0, 1);
    k_conv1x1<<<dim3(160, 1, B_), 256>>>(wg1, bg1, p_cat1, 192*NT_, p_cat1, 0, 192, 192,
                                         p_h01, 128, 64, 1);
    // fused [u | h0f | h1f] -> g_qkv
    k_conv1x1<<<dim3(160, 3, B_), 256>>>(p_w3, p_b3, p_h01, 128*NT_, p_h01, 0, 128, 128,
                                         p_qkv, 192, 0, 0);
    // fusion -> out
    k_fusion<<<(B_*NT_)/256, 256>>>(out);
}

// round 5
// speedup vs baseline: 1.4159x; 1.4159x over previous
#include <cuda_runtime.h>
#include <cuda_bf16.h>
#include <cstdint>

#define B_   16
#define N_   1024
#define TO_  20
#define JT_  327680
#define JB_  2560

#if defined(__CUDA_ARCH_FEAT_SM103_ALL) || defined(__CUDA_ARCH_FEAT_SM100_ALL)
#define TC_PATH 1
#endif

typedef __nv_bfloat16 bf16;

// ---------------- globals ----------------
__device__ float g_qkvJ[(size_t)JT_*192];
__device__ __align__(256) bf16 g_xeh[(size_t)JT_*128], g_xel[(size_t)JT_*128];
__device__ __align__(256) bf16 g_atth[(size_t)JT_*64], g_attl[(size_t)JT_*64];
__device__ __align__(256) bf16 g_hch[(size_t)JT_*320], g_hcl[(size_t)JT_*320];
__device__ __align__(256) bf16 g_xth[(size_t)20480*1024], g_xtl[(size_t)20480*1024];
__device__ __align__(256) bf16 g_h01h[(size_t)JT_*128], g_h01l[(size_t)JT_*128];
__device__ __align__(256) bf16 g_Ah[4*1024*1024], g_Al[4*1024*1024];
__device__ __align__(256) bf16 g_wqkvh[24576], g_wqkvl[24576];   // [2][192][64]
__device__ __align__(256) bf16 g_woh[4096],   g_wol[4096];       // [1][64][64]
__device__ __align__(256) bf16 g_wgh[40960],  g_wgl[40960];      // [5][128][64]
__device__ __align__(256) bf16 g_w3h[24576],  g_w3l[24576];      // [2][192][64]
__device__ float g_bqkv[192], g_bo[64], g_bh[128], g_b3u[64];

__device__ __forceinline__ float bf2f(bf16 v) { return __bfloat162float(v); }
__device__ __forceinline__ uint32_t smem_u32(const void* p) {
    uint32_t a;
    asm("{ .reg .u64 t; cvta.to.shared.u64 t, %1; cvt.u32.u64 %0, t; }" : "=r"(a) : "l"(p));
    return a;
}
__device__ __forceinline__ void cpa16(uint32_t dst, const void* src) {
    asm volatile("cp.async.cg.shared.global [%0], [%1], 16;" :: "r"(dst), "l"(src));
}
__device__ __forceinline__ void cpa_commit() { asm volatile("cp.async.commit_group;" ::: "memory"); }
__device__ __forceinline__ void cpa_wait1()  { asm volatile("cp.async.wait_group 1;" ::: "memory"); }
__device__ __forceinline__ void cpa_wait0()  { asm volatile("cp.async.wait_group 0;" ::: "memory"); }
#define SWZ(o) ((o) ^ (((o) >> 3) & 0x70))

#ifdef TC_PATH
__device__ __forceinline__ uint32_t elect1() {
    uint32_t p;
    asm volatile("{\n\t.reg .pred p;\n\telect.sync _|p, 0xFFFFFFFF;\n\tselp.b32 %0, 1, 0, p;\n\t}" : "=r"(p));
    return p;
}
#define MBARRIER_INIT(addr, cnt) \
    asm volatile("mbarrier.init.shared.b64 [%0], %1;" :: "r"(addr), "r"(cnt) : "memory")
#define MBARRIER_INVAL(addr) \
    asm volatile("mbarrier.inval.shared.b64 [%0];" :: "r"(addr) : "memory")
#define MBAR_WAIT(mb, par) do { \
    uint32_t _m = (uint32_t)(mb), _p = (uint32_t)(par), _d; \
    asm volatile("{\n\t.reg .pred p;\n\t" \
        "mbarrier.try_wait.parity.acquire.cta.shared::cta.b64 p, [%1], %2;\n\t" \
        "selp.b32 %0, 1, 0, p;\n\t}" : "=r"(_d) : "r"(_m), "r"(_p) : "memory"); \
    if (!_d) { \
        asm volatile("{\n\t.reg .pred P1;\n\t" \
            "WL_%=:\n\t" \
            "mbarrier.try_wait.parity.acquire.cta.shared::cta.b64 P1, [%0], %1, 0x989680;\n\t" \
            "@P1 bra.uni WD_%=;\n\tbra.uni WL_%=;\n\tWD_%=:\n\t}" \
            :: "r"(_m), "r"(_p) : "memory"); \
    } \
} while(0)
#define TC_ALLOC(saddr, n) \
    asm volatile("tcgen05.alloc.cta_group::1.sync.aligned.shared::cta.b32 [%0], %1;" \
        :: "r"((uint32_t)(saddr)), "r"((uint32_t)(n)) : "memory")
#define TC_DEALLOC(tmem, n) \
    asm volatile("tcgen05.dealloc.cta_group::1.sync.aligned.b32 %0, %1;" :: "r"(tmem), "r"((uint32_t)(n)))
#define TC_RELINQ() asm volatile("tcgen05.relinquish_alloc_permit.cta_group::1.sync.aligned;")
#define TC_COMMIT(mbar) \
    asm volatile("tcgen05.commit.cta_group::1.mbarrier::arrive::one.shared::cluster.b64 [%0];" \
        :: "r"((uint32_t)(mbar)) : "memory")
#define TC_FENCE_AFTER() asm volatile("tcgen05.fence::after_thread_sync;" ::: "memory")
#define TC_WAIT_LD() asm volatile("tcgen05.wait::ld.sync.aligned;" ::: "memory")
#define TC_LD_X32(r, ta) \
    asm volatile("tcgen05.ld.sync.aligned.32x32b.x32.b32 " \
        "{%0, %1, %2, %3, %4, %5, %6, %7, %8, %9, %10, %11, %12, %13, %14, %15, " \
        " %16, %17, %18, %19, %20, %21, %22, %23, %24, %25, %26, %27, %28, %29, %30, %31}, [%32];" \
        : "=r"((r)[0]),  "=r"((r)[1]),  "=r"((r)[2]),  "=r"((r)[3]), \
          "=r"((r)[4]),  "=r"((r)[5]),  "=r"((r)[6]),  "=r"((r)[7]), \
          "=r"((r)[8]),  "=r"((r)[9]),  "=r"((r)[10]), "=r"((r)[11]), \
          "=r"((r)[12]), "=r"((r)[13]), "=r"((r)[14]), "=r"((r)[15]), \
          "=r"((r)[16]), "=r"((r)[17]), "=r"((r)[18]), "=r"((r)[19]), \
          "=r"((r)[20]), "=r"((r)[21]), "=r"((r)[22]), "=r"((r)[23]), \
          "=r"((r)[24]), "=r"((r)[25]), "=r"((r)[26]), "=r"((r)[27]), \
          "=r"((r)[28]), "=r"((r)[29]), "=r"((r)[30]), "=r"((r)[31]) \
        : "r"(ta))
__device__ __forceinline__ uint64_t make_desc(uint32_t addr) {
    return 0x4000404000010000ULL | (uint64_t)((addr >> 4) & 0x3FFF);
}
__device__ __forceinline__ void mma_bf(uint32_t d, uint64_t a, uint64_t b, uint32_t idesc, bool acc) {
    uint32_t en = acc ? 1u : 0u;
    asm volatile("{\n\t.reg .pred p;\n\tsetp.ne.u32 p, %5, 0;\n\t"
        "tcgen05.mma.cta_group::1.kind::f16 [%0], %1, %2, %3, {%4, %4, %4, %4}, p;\n\t}"
        :: "r"(d), "l"(a), "l"(b), "r"(idesc), "r"(0u), "r"(en) : "memory");
}
#define IDESC(n) (0x8000490u | (((n)/8) << 17))
#endif

// ---------------- weight split/pack ----------------
__global__ void k_wsplit(const float* __restrict__ wq, const float* __restrict__ bq,
                         const float* __restrict__ wk, const float* __restrict__ bk,
                         const float* __restrict__ wv, const float* __restrict__ bv,
                         const float* __restrict__ wo, const float* __restrict__ bo,
                         const float* __restrict__ wg0, const float* __restrict__ bg0,
                         const float* __restrict__ wg1, const float* __restrict__ bg1,
                         const float* __restrict__ wadp, const float* __restrict__ badp,
                         const float* __restrict__ w0f) {
    int i = blockIdx.x * 256 + threadIdx.x;
    if (i < 24576) {
        int c = i / 12288, rem = i % 12288, r = rem / 64, k = rem & 63, col = c*64 + k;
        int s = r / 64, rr = r % 64;
        const float* W = (s == 0) ? wq : (s == 1) ? wk : wv;
        float v = (col < 96) ? W[rr*96 + col] : 0.f;
        bf16 h = __float2bfloat16(v);
        g_wqkvh[i] = h; g_wqkvl[i] = __float2bfloat16(v - bf2f(h));
    } else if (i < 28672) {
        int j = i - 24576;
        float v = wo[j];
        bf16 h = __float2bfloat16(v);
        g_woh[j] = h; g_wol[j] = __float2bfloat16(v - bf2f(h));
    } else if (i < 69632) {
        int j = i - 28672;
        int c = j / 8192, rem = j % 8192, r = rem / 64, k = rem & 63, col = c*64 + k;
        float v;
        if (r < 64) v = (col < 192) ? wg0[r*192 + col] : 0.f;
        else {
            int rr = r - 64;
            if (col < 64) v = wg1[rr*192 + col];
            else if (col >= 192) v = wg1[rr*192 + col - 128];
            else v = 0.f;
        }
        bf16 h = __float2bfloat16(v);
        g_wgh[j] = h; g_wgl[j] = __float2bfloat16(v - bf2f(h));
    } else if (i < 94208) {
        int j = i - 69632;
        int c = j / 12288, rem = j % 12288, r = rem / 64, k = rem & 63, col = c*64 + k;
        float v;
        if (r < 64)       v = wadp[r*128 + col];
        else if (r < 128) v = (col < 64) ? w0f[(r-64)*64 + col] : 0.f;
        else              v = (col >= 64) ? w0f[(r-128)*64 + col - 64] : 0.f;
        bf16 h = __float2bfloat16(v);
        g_w3h[j] = h; g_w3l[j] = __float2bfloat16(v - bf2f(h));
    } else if (i < 94656) {
        int j = i - 94208;
        if (j < 192)      g_bqkv[j] = (j < 64) ? bq[j] : (j < 128) ? bk[j-64] : bv[j-128];
        else if (j < 256) g_bo[j-192] = bo[j-192];
        else if (j < 384) { int j2 = j-256; g_bh[j2] = (j2 < 64) ? bg0[j2] : bg1[j2-64]; }
        else              g_b3u[j-384] = badp[j-384];
    }
}

__global__ void k_split_A(const float* __restrict__ A0, const float* __restrict__ A1,
                          const float* __restrict__ A2, const float* __restrict__ A3) {
    int i = blockIdx.x * 256 + threadIdx.x;
    int z = i >> 20, r = i & 1048575;
    const float* A = (z == 0) ? A0 : (z == 1) ? A1 : (z == 2) ? A2 : A3;
    float v = A[r];
    bf16 h = __float2bfloat16(v);
    g_Ah[i] = h;
    g_Al[i] = __float2bfloat16(v - bf2f(h));
}

// ---------------- fused dilated conv + tem slice -> xe[J][128] h/l ----------------
__global__ __launch_bounds__(256) void k_xe(const float* __restrict__ x,
                                            const float* __restrict__ tem,
                                            const float* __restrict__ w,
                                            const float* __restrict__ bias) {
    __shared__ float pool[9376];
    float* xs = pool;            // [4][32][24]
    float* ws = pool + 3072;     // [96][65]
    float* bs = pool + 9312;
    int tid = threadIdx.x;
    int b = blockIdx.x >> 8, n0 = (blockIdx.x & 255) * 4;
    for (int i = tid; i < 64*96; i += 256) { int o = i / 96, kk = i % 96; ws[kk*65 + o] = w[i]; }
    if (tid < 64) bs[tid] = bias[tid];
    for (int i = tid; i < 3072; i += 256) {
        int nn = i / 768, r = i % 768, ci = r / 24, tt = r % 24;
        xs[(nn*32 + ci)*24 + tt] = x[((size_t)(b*32 + ci)*1024 + n0 + nn)*24 + tt];
    }
    __syncthreads();
    int co = tid & 63, nn = tid >> 6;
    float acc[20];
#pragma unroll
    for (int t = 0; t < 20; t++) acc[t] = bs[co];
    for (int ci = 0; ci < 32; ci++) {
        float w0 = ws[(ci*3+0)*65 + co], w1 = ws[(ci*3+1)*65 + co], w2 = ws[(ci*3+2)*65 + co];
        const float* xr = &xs[(nn*32 + ci)*24];
#pragma unroll
        for (int t = 0; t < 20; t++) acc[t] += w0*xr[t] + w1*xr[t+2] + w2*xr[t+4];
    }
    __syncthreads();
    float* sxe = pool;           // [80][96]
#pragma unroll
    for (int t = 0; t < 20; t++) sxe[(nn*20 + t)*96 + co] = fmaxf(acc[t], 0.f);
    for (int i = tid; i < 2560; i += 256) {
        int nn2 = i / 640, r = i % 640, ci = r / 20, t = r % 20;
        sxe[(nn2*20 + t)*96 + 64 + ci] = tem[((size_t)(b*32 + ci)*1024 + n0 + nn2)*24 + 4 + t];
    }
    __syncthreads();
    if (tid < 160) {
        int half = tid / 80, rr = tid % 80;
        int nn2 = rr / 20, t = rr % 20;
        size_t J = (size_t)((b*1024 + n0 + nn2)*20 + t);
        bf16* dst = (half ? g_xel : g_xeh) + J*128;
        const float* srow = &sxe[rr*96];
        for (int cb = 0; cb < 128; cb += 8) {
            bf16 tmp[8];
#pragma unroll
            for (int u = 0; u < 8; u++) {
                float vv = (cb + u < 96) ? srow[cb + u] : 0.f;
                bf16 hv = __float2bfloat16(vv);
                tmp[u] = half ? __float2bfloat16(vv - bf2f(hv)) : hv;
            }
            *(uint4*)(dst + cb) = *(uint4*)tmp;
        }
    }
}

// ---------------- generic tensor-core GEMM over J rows ----------------
struct GemmArgs {
    const bf16 *ah, *al;      // activations [J][K]
    const bf16 *wh, *wl;      // weights [K/64][N][64]
    const float* bias;
    float* outf;              // MODE 0
    bf16 *oh, *ol;            // MODE 1/2
    int opitch;
    float* outfin;            // MODE 3
};

// MODE 0: fp32 [J][192]+bias  1: relu+bias split, pitch opitch  2: same  3: fused fusion
template<int K_, int NN, int MODE>
__global__ __launch_bounds__(256) void k_gemm(GemmArgs p) {
    constexpr int NCH = K_ / 64;
    constexpr int WB  = NN * 128;
    constexpr int STG = 32768 + 2*WB;
    constexpr int DP  = NN + 4;
    extern __shared__ char smem[];
    int tid = threadIdx.x, wid = tid >> 5, lane = tid & 31;
    int J0 = blockIdx.x * 128;
    float* Dt = (float*)(smem + 1024);   // [128][DP]

#ifdef TC_PATH
    uint32_t sb = smem_u32(smem);
    if (wid == 0) TC_ALLOC(sb, 256);
    if (tid == 0) { MBARRIER_INIT(sb+8, 1); MBARRIER_INIT(sb+16, 1); }
    __syncthreads();
    uint32_t tmem;
    asm volatile("ld.shared.b32 %0, [%1];" : "=r"(tmem) : "r"(sb));
    uint32_t bufb = sb + 1024;

    auto load_chunk = [&](int c, uint32_t st) {
        for (int i = tid; i < 2048 + 2*NN*8; i += 256) {
            uint32_t dst; const void* src;
            if (i < 2048) {
                int part = i >> 10, e = i & 1023, r = e >> 3, c8 = e & 7;
                src = (part ? p.al : p.ah) + (size_t)(J0 + r)*K_ + c*64 + c8*8;
                dst = st + part*16384 + SWZ(r*128 + c8*16);
            } else {
                int j = i - 2048;
                int part = (j >= NN*8);
                int e = part ? j - NN*8 : j;
                int r = e >> 3, c8 = e & 7;
                src = (part ? p.wl : p.wh) + ((size_t)c*NN + r)*64 + c8*8;
                dst = st + 32768 + part*WB + SWZ(r*128 + c8*16);
            }
            cpa16(dst, src);
        }
    };

    load_chunk(0, bufb);
    cpa_commit();
    int ph0 = 0, ph1 = 0;
    for (int ch = 0; ch < NCH; ch++) {
        int buf = ch & 1;
        if (ch + 1 < NCH) {
            int nb = 1 - buf;
            if (ch >= 1) {
                MBAR_WAIT(sb + 8 + 8*nb, (nb == 0) ? ph0 : ph1);
                if (nb == 0) ph0 ^= 1; else ph1 ^= 1;
            }
            load_chunk(ch+1, bufb + STG*nb);
            cpa_commit();
            cpa_wait1();
        } else {
            cpa_wait0();
        }
        __syncthreads();
        if (wid == 0) {
            asm volatile("fence.proxy.async.shared::cta;" ::: "memory");
            if (elect1()) {
                uint32_t s0 = bufb + STG*buf;
                uint64_t ah = make_desc(s0);
                uint64_t al = make_desc(s0 + 16384);
                uint64_t wh = make_desc(s0 + 32768);
                uint64_t wl = make_desc(s0 + 32768 + WB);
#pragma unroll
                for (int ks = 0; ks < 4; ks++) {
                    mma_bf(tmem, ah + 2*ks, wh + 2*ks, IDESC(NN), !(ch == 0 && ks == 0));
                    mma_bf(tmem, ah + 2*ks, wl + 2*ks, IDESC(NN), true);
                    mma_bf(tmem, al + 2*ks, wh + 2*ks, IDESC(NN), true);
                }
                TC_COMMIT(sb + 8 + 8*buf);
            }
        }
    }
    {
        int lb = (NCH - 1) & 1;
        MBAR_WAIT(sb + 8 + 8*lb, lb ? ph1 : ph0);
    }
    TC_FENCE_AFTER();
    __syncthreads();
    {
        int sub = wid & 3, g = wid >> 2;
        int m = sub*32 + lane;
        for (int ci = g; ci < NN/32; ci += 2) {
            uint32_t r[32];
            TC_LD_X32(r, tmem + ci*32);
            TC_WAIT_LD();
#pragma unroll
            for (int c = 0; c < 32; c++) Dt[m*DP + ci*32 + c] = __uint_as_float(r[c]);
        }
    }
    __syncthreads();
    if (tid == 0) { MBARRIER_INVAL(sb+8); MBARRIER_INVAL(sb+16); }
    if (wid == 0) { TC_RELINQ(); TC_DEALLOC(tmem, 256); }
    __syncthreads();
#else
    for (int idx = tid; idx < 128*NN; idx += 256) {
        int m = idx / NN, n = idx % NN;
        float acc = 0.f;
        for (int k = 0; k < K_; k++) {
            float av = bf2f(p.ah[(size_t)(J0+m)*K_ + k]) + bf2f(p.al[(size_t)(J0+m)*K_ + k]);
            size_t wi = ((size_t)(k/64)*NN + n)*64 + (k & 63);
            acc += av * (bf2f(p.wh[wi]) + bf2f(p.wl[wi]));
        }
        Dt[m*DP + n] = acc;
    }
    __syncthreads();
#endif

    // ---- epilogues ----
    int m = tid >> 1, half = tid & 1;
    if (MODE == 0) {
        size_t ob = (size_t)(J0 + m)*192 + half*96;
        for (int c = 0; c < 96; c += 4) {
            float4 v;
            v.x = Dt[m*DP + half*96 + c + 0] + p.bias[half*96 + c + 0];
            v.y = Dt[m*DP + half*96 + c + 1] + p.bias[half*96 + c + 1];
            v.z = Dt[m*DP + half*96 + c + 2] + p.bias[half*96 + c + 2];
            v.w = Dt[m*DP + half*96 + c + 3] + p.bias[half*96 + c + 3];
            *(float4*)(p.outf + ob + c) = v;
        }
    } else if (MODE == 1 || MODE == 2) {
        const int ncols = NN / 2;
        int base = half * ncols;
        size_t ob = (size_t)(J0 + m) * p.opitch + base;
        for (int cb = 0; cb < ncols; cb += 8) {
            bf16 th[8], tl[8];
#pragma unroll
            for (int u = 0; u < 8; u++) {
                int c = base + cb + u;
                float v = fmaxf(Dt[m*DP + c] + p.bias[c], 0.f);
                bf16 hv = __float2bfloat16(v);
                th[u] = hv;
                tl[u] = __float2bfloat16(v - bf2f(hv));
            }
            *(uint4*)(p.oh + ob + cb) = *(uint4*)th;
            *(uint4*)(p.ol + ob + cb) = *(uint4*)tl;
        }
    } else {
        float s0 = 0.f, s1 = 0.f;
        for (int c = half*32; c < half*32 + 32; c++) {
            float u = Dt[m*DP + c] + p.bias[c];
            s0 += Dt[m*DP + 64 + c]  * u;
            s1 += Dt[m*DP + 128 + c] * u;
        }
        s0 += __shfl_xor_sync(0xffffffffu, s0, 1);
        s1 += __shfl_xor_sync(0xffffffffu, s1, 1);
        float mx = fmaxf(s0, s1);
        float e0 = __expf(s0 - mx), e1 = __expf(s1 - mx);
        float inv = 1.f / (e0 + e1);
        float a0 = e0*inv, a1 = e1*inv;
        int J = J0 + m;
        int b = J / 20480, r = J % 20480, n = r / 20, t = r % 20;
        for (int c = half*32; c < half*32 + 32; c++) {
            float v = a0*Dt[m*DP + 64 + c] + a1*Dt[m*DP + 128 + c];
            p.outfin[((size_t)(b*64 + c)*1024 + n)*20 + t] = v;
        }
    }
}

// ---------------- attention: warp per (b, h, n) ----------------
__global__ __launch_bounds__(256) void k_attn() {
    __shared__ float sbuf[8][880];
    int warp = threadIdx.x >> 5, lane = threadIdx.x & 31;
    int g = blockIdx.x * 8 + warp;
    int b = g >> 13, h = (g >> 10) & 7, n = g & 1023;
    float* q = sbuf[warp];
    float* k = q + 160;
    float* v = k + 160;
    float* S = v + 160;
    size_t Jb = (size_t)(b*1024 + n)*20;

    for (int idx = lane; idx < 160; idx += 32) {
        int d = idx / 20, t = idx % 20;
        size_t row = (Jb + t)*192 + h*8 + d;
        q[idx] = g_qkvJ[row];
        k[idx] = g_qkvJ[row + 64];
        v[idx] = g_qkvJ[row + 128];
    }
    __syncwarp();
    for (int idx = lane; idx < 400; idx += 32) {
        int t = idx / 20, s = idx % 20;
        if (s <= t) {
            float acc = 0.f;
#pragma unroll
            for (int d = 0; d < 8; d++) acc += q[d*20 + t] * k[d*20 + s];
            S[idx] = acc * 0.35355339059327373f;
        }
    }
    __syncwarp();
    if (lane < 20) {
        int t = lane;
        float mx = -1e30f;
        for (int s = 0; s <= t; s++) mx = fmaxf(mx, S[t*20 + s]);
        float sum = 0.f;
        for (int s = 0; s <= t; s++) { float e = __expf(S[t*20 + s] - mx); S[t*20 + s] = e; sum += e; }
        float inv = 1.f / sum;
        for (int s = 0; s <= t; s++) S[t*20 + s] *= inv;
    }
    __syncwarp();
    // o overwrites q
    for (int idx = lane; idx < 160; idx += 32) {
        int d = idx / 20, t = idx % 20;
        float acc = 0.f;
        for (int s = 0; s <= t; s++) acc += S[t*20 + s] * v[d*20 + s];
        q[idx] = acc;
    }
    __syncwarp();
    if (lane < 20) {
        int t = lane;
        bf16 th[8], tl[8];
#pragma unroll
        for (int d = 0; d < 8; d++) {
            float vv = q[d*20 + t];
            bf16 hv = __float2bfloat16(vv);
            th[d] = hv;
            tl[d] = __float2bfloat16(vv - bf2f(hv));
        }
        size_t ob = (Jb + t)*64 + h*8;
        *(uint4*)(g_atth + ob) = *(uint4*)th;
        *(uint4*)(g_attl + ob) = *(uint4*)tl;
    }
}

// ---------------- transpose x2 (hcat cols 0-63) -> xt[(b,t,c)][n] ----------------
__global__ __launch_bounds__(256) void k_xt() {
    __shared__ bf16 th[64][72], tl[64][72];
    int tid = threadIdx.x;
    int b = blockIdx.x, t = blockIdx.y, n0 = blockIdx.z * 64;
    for (int i = tid; i < 512; i += 256) {
        int r = i >> 3, c8 = i & 7;
        size_t src = ((size_t)(b*1024 + n0 + r)*20 + t)*320 + c8*8;
        *(uint4*)(&th[r][c8*8]) = *(const uint4*)(g_hch + src);
        *(uint4*)(&tl[r][c8*8]) = *(const uint4*)(g_hcl + src);
    }
    __syncthreads();
    for (int i = tid; i < 512; i += 256) {
        int c = i >> 3, n8 = i & 7;
        bf16 vh[8], vl[8];
#pragma unroll
        for (int u = 0; u < 8; u++) { vh[u] = th[n8*8 + u][c]; vl[u] = tl[n8*8 + u][c]; }
        size_t dst = (size_t)(b*1280 + t*64 + c)*1024 + n0 + n8*8;
        *(uint4*)(g_xth + dst) = *(uint4*)vh;
        *(uint4*)(g_xtl + dst) = *(uint4*)vl;
    }
}

// ---------------- nconv: D[128 w][256 j'=(t,c)] ----------------
#define NSTG 98304
#define NSMEM (1024 + 2*NSTG)
__device__ __forceinline__ void nc_load(int k0, uint32_t st,
                                        const bf16* Ah, const bf16* Al,
                                        int m0, int j0, int tid) {
    for (int g = tid; g < 6144; g += 256) {
        uint32_t dst; const void* src;
        if (g < 2048) {
            int part = g >> 10, e = g & 1023, r = e >> 3, c8 = e & 7;
            src = (part ? Al : Ah) + (size_t)(m0 + r)*1024 + k0 + c8*8;
            dst = st + part*16384 + SWZ(r*128 + c8*16);
        } else {
            int j = g - 2048;
            int part = j >> 11, e = j & 2047, r = e >> 3, c8 = e & 7;
            src = (part ? g_xtl : g_xth) + (size_t)(j0 + r)*1024 + k0 + c8*8;
            dst = st + 32768 + part*32768 + SWZ(r*128 + c8*16);
        }
        cpa16(dst, src);
    }
}

__global__ __launch_bounds__(256) void k_nconv_tc() {
    extern __shared__ char smem[];
    int tid = threadIdx.x, wid = tid >> 5, lane = tid & 31;
    int j0 = blockIdx.x * 256, m0 = blockIdx.y * 128, z = blockIdx.z;
    const bf16* Ah = g_Ah + (size_t)z*1024*1024;
    const bf16* Al = g_Al + (size_t)z*1024*1024;
    float* Dt = (float*)(smem + 1024);          // [256 j'][129]

#ifdef TC_PATH
    uint32_t sb = smem_u32(smem);
    if (wid == 0) TC_ALLOC(sb, 256);
    if (tid == 0) { MBARRIER_INIT(sb+8, 1); MBARRIER_INIT(sb+16, 1); }
    __syncthreads();
    uint32_t tmem;
    asm volatile("ld.shared.b32 %0, [%1];" : "=r"(tmem) : "r"(sb));
    uint32_t bufb = sb + 1024;

    nc_load(0, bufb, Ah, Al, m0, j0, tid);
    cpa_commit();
    int ph0 = 0, ph1 = 0;
    for (int ch = 0; ch < 16; ch++) {
        int buf = ch & 1;
        if (ch + 1 < 16) {
            int nb = 1 - buf;
            if (ch >= 1) {
                MBAR_WAIT(sb + 8 + 8*nb, (nb == 0) ? ph0 : ph1);
                if (nb == 0) ph0 ^= 1; else ph1 ^= 1;
            }
            nc_load((ch+1)*64, bufb + NSTG*nb, Ah, Al, m0, j0, tid);
            cpa_commit();
            cpa_wait1();
        } else {
            cpa_wait0();
        }
        __syncthreads();
        if (wid == 0) {
            asm volatile("fence.proxy.async.shared::cta;" ::: "memory");
            if (elect1()) {
                uint32_t s0 = bufb + NSTG*buf;
                uint64_t ah = make_desc(s0);
                uint64_t al = make_desc(s0 + 16384);
                uint64_t xh = make_desc(s0 + 32768);
                uint64_t xl = make_desc(s0 + 65536);
#pragma unroll
                for (int ks = 0; ks < 4; ks++) {
                    mma_bf(tmem, ah + 2*ks, xh + 2*ks, IDESC(256), !(ch == 0 && ks == 0));
                    mma_bf(tmem, ah + 2*ks, xl + 2*ks, IDESC(256), true);
                    mma_bf(tmem, al + 2*ks, xh + 2*ks, IDESC(256), true);
                }
                TC_COMMIT(sb + 8 + 8*buf);
            }
        }
    }
    MBAR_WAIT(sb + 16, ph1);
    TC_FENCE_AFTER();
    __syncthreads();
    {
        int sub = wid & 3, hf = wid >> 2;
        int m = sub*32 + lane;
#pragma unroll
        for (int i = 0; i < 4; i++) {
            uint32_t r[32];
            int cb = hf*128 + i*32;
            TC_LD_X32(r, tmem + cb);
            TC_WAIT_LD();
#pragma unroll
            for (int c = 0; c < 32; c++) Dt[(cb + c)*129 + m] = __uint_as_float(r[c]);
        }
    }
    __syncthreads();
    if (tid == 0) { MBARRIER_INVAL(sb+8); MBARRIER_INVAL(sb+16); }
    if (wid == 0) { TC_RELINQ(); TC_DEALLOC(tmem, 256); }
    __syncthreads();
#else
    for (int idx = tid; idx < 128*256; idx += 256) {
        int m = idx >> 8, jl = idx & 255;
        float acc = 0.f;
        for (int kk = 0; kk < 1024; kk++) {
            float av = bf2f(Ah[(size_t)(m0+m)*1024 + kk]) + bf2f(Al[(size_t)(m0+m)*1024 + kk]);
            float xv = bf2f(g_xth[(size_t)(j0+jl)*1024 + kk]) + bf2f(g_xtl[(size_t)(j0+jl)*1024 + kk]);
            acc += av * xv;
        }
        Dt[jl*129 + m] = acc;
    }
    __syncthreads();
#endif

    // epilogue: [128 w][4 t][64 c] -> hcat[(b,w,t)][64+z*64+c] h/l
    int b = j0 / 1280, t0 = (j0 % 1280) / 64;
    for (int task = tid; task < 512; task += 256) {
        int w = task >> 2, tq = task & 3;
        size_t J = (size_t)(b*1024 + m0 + w)*20 + t0 + tq;
        size_t ob = J*320 + 64 + z*64;
        for (int cb = 0; cb < 64; cb += 8) {
            bf16 th[8], tl[8];
#pragma unroll
            for (int u = 0; u < 8; u++) {
                float vv = Dt[(tq*64 + cb + u)*129 + w];
                bf16 hv = __float2bfloat16(vv);
                th[u] = hv;
                tl[u] = __float2bfloat16(vv - bf2f(hv));
            }
            *(uint4*)(g_hch + ob + cb) = *(uint4*)th;
            *(uint4*)(g_hcl + ob + cb) = *(uint4*)tl;
        }
    }
}

// ---------------- launch ----------------
extern "C" void kernel_launch(void* const* d_in, const int* in_sizes, int n_in,
                              void* d_out, int out_size) {
    const float* x    = (const float*)d_in[0];
    const float* tem  = (const float*)d_in[1];
    const float* A0   = (const float*)d_in[2];
    const float* A1   = (const float*)d_in[3];
    const float* A2   = (const float*)d_in[4];
    const float* A3   = (const float*)d_in[5];
    const float* w_tc = (const float*)d_in[6];
    const float* b_tc = (const float*)d_in[7];
    float* out = (float*)d_out;

    GemmArgs base = {};
    float *p_qkvJ, *p_bqkv, *p_bo, *p_bh, *p_b3u;
    cudaGetSymbolAddress((void**)&p_qkvJ, g_qkvJ);
    cudaGetSymbolAddress((void**)&p_bqkv, g_bqkv);
    cudaGetSymbolAddress((void**)&p_bo,   g_bo);
    cudaGetSymbolAddress((void**)&p_bh,   g_bh);
    cudaGetSymbolAddress((void**)&p_b3u,  g_b3u);
    bf16 *p_xeh, *p_xel, *p_atth, *p_attl, *p_hch, *p_hcl, *p_h01h, *p_h01l;
    bf16 *p_wqkvh, *p_wqkvl, *p_woh, *p_wol, *p_wgh, *p_wgl, *p_w3h, *p_w3l;
    cudaGetSymbolAddress((void**)&p_xeh, g_xeh);   cudaGetSymbolAddress((void**)&p_xel, g_xel);
    cudaGetSymbolAddress((void**)&p_atth, g_atth); cudaGetSymbolAddress((void**)&p_attl, g_attl);
    cudaGetSymbolAddress((void**)&p_hch, g_hch);   cudaGetSymbolAddress((void**)&p_hcl, g_hcl);
    cudaGetSymbolAddress((void**)&p_h01h, g_h01h); cudaGetSymbolAddress((void**)&p_h01l, g_h01l);
    cudaGetSymbolAddress((void**)&p_wqkvh, g_wqkvh); cudaGetSymbolAddress((void**)&p_wqkvl, g_wqkvl);
    cudaGetSymbolAddress((void**)&p_woh, g_woh);   cudaGetSymbolAddress((void**)&p_wol, g_wol);
    cudaGetSymbolAddress((void**)&p_wgh, g_wgh);   cudaGetSymbolAddress((void**)&p_wgl, g_wgl);
    cudaGetSymbolAddress((void**)&p_w3h, g_w3h);   cudaGetSymbolAddress((void**)&p_w3l, g_w3l);

    const int S_QKV = 1024 + 2*(32768 + 2*192*128);
    const int S_WO  = 1024 + 2*(32768 + 2*64*128);
    const int S_H   = 1024 + 2*(32768 + 2*128*128);
    cudaFuncSetAttribute(k_gemm<128,192,0>, cudaFuncAttributeMaxDynamicSharedMemorySize, S_QKV);
    cudaFuncSetAttribute(k_gemm<64,64,1>,   cudaFuncAttributeMaxDynamicSharedMemorySize, S_WO);
    cudaFuncSetAttribute(k_gemm<320,128,2>, cudaFuncAttributeMaxDynamicSharedMemorySize, S_H);
    cudaFuncSetAttribute(k_gemm<128,192,3>, cudaFuncAttributeMaxDynamicSharedMemorySize, S_QKV);
    cudaFuncSetAttribute(k_nconv_tc,        cudaFuncAttributeMaxDynamicSharedMemorySize, NSMEM);

    k_wsplit<<<370, 256>>>(
        (const float*)d_in[8],  (const float*)d_in[9],
        (const float*)d_in[10], (const float*)d_in[11],
        (const float*)d_in[12], (const float*)d_in[13],
        (const float*)d_in[14], (const float*)d_in[15],
        (const float*)d_in[16], (const float*)d_in[17],
        (const float*)d_in[18], (const float*)d_in[19],
        (const float*)d_in[20], (const float*)d_in[21],
        (const float*)d_in[22]);
    k_split_A<<<16384, 256>>>(A0, A1, A2, A3);
    k_xe<<<4096, 256>>>(x, tem, w_tc, b_tc);

    GemmArgs a = base;
    a.ah = p_xeh; a.al = p_xel; a.wh = p_wqkvh; a.wl = p_wqkvl;
    a.bias = p_bqkv; a.outf = p_qkvJ;
    k_gemm<128,192,0><<<JB_, 256, S_QKV>>>(a);

    k_attn<<<16384, 256>>>();

    a = base;
    a.ah = p_atth; a.al = p_attl; a.wh = p_woh; a.wl = p_wol;
    a.bias = p_bo; a.oh = p_hch; a.ol = p_hcl; a.opitch = 320;
    k_gemm<64,64,1><<<JB_, 256, S_WO>>>(a);

    k_xt<<<dim3(16, 20, 16), 256>>>();
    k_nconv_tc<<<dim3(80, 8, 4), 256, NSMEM>>>();

    a = base;
    a.ah = p_hch; a.al = p_hcl; a.wh = p_wgh; a.wl = p_wgl;
    a.bias = p_bh; a.oh = p_h01h; a.ol = p_h01l; a.opitch = 128;
    k_gemm<320,128,2><<<JB_, 256, S_H>>>(a);

    a = base;
    a.ah = p_h01h; a.al = p_h01l; a.wh = p_w3h; a.wl = p_w3l;
    a.bias = p_b3u; a.outfin = out;
    k_gemm<128,192,3><<<JB_, 256, S_QKV>>>(a);
}

// round 6
// speedup vs baseline: 1.4396x; 1.0167x over previous
#include <cuda_runtime.h>
#include <cuda_bf16.h>
#include <cstdint>

#define B_   16
#define N_   1024
#define TO_  20
#define JT_  327680
#define JPB  8
#define GB_  320

#if defined(__CUDA_ARCH_FEAT_SM103_ALL) || defined(__CUDA_ARCH_FEAT_SM100_ALL)
#define TC_PATH 1
#endif

typedef __nv_bfloat16 bf16;

__device__ float g_qkvJ[(size_t)JT_*192];
__device__ __align__(256) bf16 g_xeh[(size_t)JT_*128], g_xel[(size_t)JT_*128];
__device__ __align__(256) bf16 g_atth[(size_t)JT_*64], g_attl[(size_t)JT_*64];
__device__ __align__(256) bf16 g_hch[(size_t)JT_*320], g_hcl[(size_t)JT_*320];
__device__ __align__(256) bf16 g_xth[(size_t)20480*1024], g_xtl[(size_t)20480*1024];
__device__ __align__(256) bf16 g_h01h[(size_t)JT_*128], g_h01l[(size_t)JT_*128];
__device__ __align__(256) bf16 g_Ah[4*1024*1024], g_Al[4*1024*1024];
__device__ __align__(256) bf16 g_wqkvh[24576], g_wqkvl[24576];
__device__ __align__(256) bf16 g_woh[4096],   g_wol[4096];
__device__ __align__(256) bf16 g_wgh[40960],  g_wgl[40960];
__device__ __align__(256) bf16 g_w3h[24576],  g_w3l[24576];
__device__ float g_bqkv[192], g_bo[64], g_bh[128], g_b3u[64];

__device__ __forceinline__ float bf2f(bf16 v) { return __bfloat162float(v); }
__device__ __forceinline__ uint32_t smem_u32(const void* p) {
    uint32_t a;
    asm("{ .reg .u64 t; cvta.to.shared.u64 t, %1; cvt.u32.u64 %0, t; }" : "=r"(a) : "l"(p));
    return a;
}
__device__ __forceinline__ void cpa16(uint32_t dst, const void* src) {
    asm volatile("cp.async.cg.shared.global [%0], [%1], 16;" :: "r"(dst), "l"(src));
}
__device__ __forceinline__ void cpa_commit() { asm volatile("cp.async.commit_group;" ::: "memory"); }
__device__ __forceinline__ void cpa_wait1()  { asm volatile("cp.async.wait_group 1;" ::: "memory"); }
__device__ __forceinline__ void cpa_wait0()  { asm volatile("cp.async.wait_group 0;" ::: "memory"); }
#define SWZ(o) ((o) ^ (((o) >> 3) & 0x70))

#ifdef TC_PATH
__device__ __forceinline__ uint32_t elect1() {
    uint32_t p;
    asm volatile("{\n\t.reg .pred p;\n\telect.sync _|p, 0xFFFFFFFF;\n\tselp.b32 %0, 1, 0, p;\n\t}" : "=r"(p));
    return p;
}
#define MBARRIER_INIT(addr, cnt) \
    asm volatile("mbarrier.init.shared.b64 [%0], %1;" :: "r"(addr), "r"(cnt) : "memory")
#define MBARRIER_INVAL(addr) \
    asm volatile("mbarrier.inval.shared.b64 [%0];" :: "r"(addr) : "memory")
#define MBAR_WAIT(mb, par) do { \
    uint32_t _m = (uint32_t)(mb), _p = (uint32_t)(par), _d; \
    asm volatile("{\n\t.reg .pred p;\n\t" \
        "mbarrier.try_wait.parity.acquire.cta.shared::cta.b64 p, [%1], %2;\n\t" \
        "selp.b32 %0, 1, 0, p;\n\t}" : "=r"(_d) : "r"(_m), "r"(_p) : "memory"); \
    if (!_d) { \
        asm volatile("{\n\t.reg .pred P1;\n\t" \
            "WL_%=:\n\t" \
            "mbarrier.try_wait.parity.acquire.cta.shared::cta.b64 P1, [%0], %1, 0x989680;\n\t" \
            "@P1 bra.uni WD_%=;\n\tbra.uni WL_%=;\n\tWD_%=:\n\t}" \
            :: "r"(_m), "r"(_p) : "memory"); \
    } \
} while(0)
#define TC_ALLOC(saddr, n) \
    asm volatile("tcgen05.alloc.cta_group::1.sync.aligned.shared::cta.b32 [%0], %1;" \
        :: "r"((uint32_t)(saddr)), "r"((uint32_t)(n)) : "memory")
#define TC_DEALLOC(tmem, n) \
    asm volatile("tcgen05.dealloc.cta_group::1.sync.aligned.b32 %0, %1;" :: "r"(tmem), "r"((uint32_t)(n)))
#define TC_RELINQ() asm volatile("tcgen05.relinquish_alloc_permit.cta_group::1.sync.aligned;")
#define TC_COMMIT(mbar) \
    asm volatile("tcgen05.commit.cta_group::1.mbarrier::arrive::one.shared::cluster.b64 [%0];" \
        :: "r"((uint32_t)(mbar)) : "memory")
#define TC_FENCE_AFTER() asm volatile("tcgen05.fence::after_thread_sync;" ::: "memory")
#define TC_WAIT_LD() asm volatile("tcgen05.wait::ld.sync.aligned;" ::: "memory")
#define TC_LD_X32(r, ta) \
    asm volatile("tcgen05.ld.sync.aligned.32x32b.x32.b32 " \
        "{%0, %1, %2, %3, %4, %5, %6, %7, %8, %9, %10, %11, %12, %13, %14, %15, " \
        " %16, %17, %18, %19, %20, %21, %22, %23, %24, %25, %26, %27, %28, %29, %30, %31}, [%32];" \
        : "=r"((r)[0]),  "=r"((r)[1]),  "=r"((r)[2]),  "=r"((r)[3]), \
          "=r"((r)[4]),  "=r"((r)[5]),  "=r"((r)[6]),  "=r"((r)[7]), \
          "=r"((r)[8]),  "=r"((r)[9]),  "=r"((r)[10]), "=r"((r)[11]), \
          "=r"((r)[12]), "=r"((r)[13]), "=r"((r)[14]), "=r"((r)[15]), \
          "=r"((r)[16]), "=r"((r)[17]), "=r"((r)[18]), "=r"((r)[19]), \
          "=r"((r)[20]), "=r"((r)[21]), "=r"((r)[22]), "=r"((r)[23]), \
          "=r"((r)[24]), "=r"((r)[25]), "=r"((r)[26]), "=r"((r)[27]), \
          "=r"((r)[28]), "=r"((r)[29]), "=r"((r)[30]), "=r"((r)[31]) \
        : "r"(ta))
__device__ __forceinline__ uint64_t make_desc(uint32_t addr) {
    return 0x4000404000010000ULL | (uint64_t)((addr >> 4) & 0x3FFF);
}
__device__ __forceinline__ void mma_bf(uint32_t d, uint64_t a, uint64_t b, uint32_t idesc, bool acc) {
    uint32_t en = acc ? 1u : 0u;
    asm volatile("{\n\t.reg .pred p;\n\tsetp.ne.u32 p, %5, 0;\n\t"
        "tcgen05.mma.cta_group::1.kind::f16 [%0], %1, %2, %3, {%4, %4, %4, %4}, p;\n\t}"
        :: "r"(d), "l"(a), "l"(b), "r"(idesc), "r"(0u), "r"(en) : "memory");
}
#define IDESC(n) (0x8000490u | (((n)/8) << 17))
#endif

// ---------------- weight split/pack ----------------
__global__ void k_wsplit(const float* __restrict__ wq, const float* __restrict__ bq,
                         const float* __restrict__ wk, const float* __restrict__ bk,
                         const float* __restrict__ wv, const float* __restrict__ bv,
                         const float* __restrict__ wo, const float* __restrict__ bo,
                         const float* __restrict__ wg0, const float* __restrict__ bg0,
                         const float* __restrict__ wg1, const float* __restrict__ bg1,
                         const float* __restrict__ wadp, const float* __restrict__ badp,
                         const float* __restrict__ w0f) {
    int i = blockIdx.x * 256 + threadIdx.x;
    if (i < 24576) {
        int c = i / 12288, rem = i % 12288, r = rem / 64, k = rem & 63, col = c*64 + k;
        int s = r / 64, rr = r % 64;
        const float* W = (s == 0) ? wq : (s == 1) ? wk : wv;
        float v = (col < 96) ? W[rr*96 + col] : 0.f;
        bf16 h = __float2bfloat16(v);
        g_wqkvh[i] = h; g_wqkvl[i] = __float2bfloat16(v - bf2f(h));
    } else if (i < 28672) {
        int j = i - 24576;
        float v = wo[j];
        bf16 h = __float2bfloat16(v);
        g_woh[j] = h; g_wol[j] = __float2bfloat16(v - bf2f(h));
    } else if (i < 69632) {
        int j = i - 28672;
        int c = j / 8192, rem = j % 8192, r = rem / 64, k = rem & 63, col = c*64 + k;
        float v;
        if (r < 64) v = (col < 192) ? wg0[r*192 + col] : 0.f;
        else {
            int rr = r - 64;
            if (col < 64) v = wg1[rr*192 + col];
            else if (col >= 192) v = wg1[rr*192 + col - 128];
            else v = 0.f;
        }
        bf16 h = __float2bfloat16(v);
        g_wgh[j] = h; g_wgl[j] = __float2bfloat16(v - bf2f(h));
    } else if (i < 94208) {
        int j = i - 69632;
        int c = j / 12288, rem = j % 12288, r = rem / 64, k = rem & 63, col = c*64 + k;
        float v;
        if (r < 64)       v = wadp[r*128 + col];
        else if (r < 128) v = (col < 64) ? w0f[(r-64)*64 + col] : 0.f;
        else              v = (col >= 64) ? w0f[(r-128)*64 + col - 64] : 0.f;
        bf16 h = __float2bfloat16(v);
        g_w3h[j] = h; g_w3l[j] = __float2bfloat16(v - bf2f(h));
    } else if (i < 94656) {
        int j = i - 94208;
        if (j < 192)      g_bqkv[j] = (j < 64) ? bq[j] : (j < 128) ? bk[j-64] : bv[j-128];
        else if (j < 256) g_bo[j-192] = bo[j-192];
        else if (j < 384) { int j2 = j-256; g_bh[j2] = (j2 < 64) ? bg0[j2] : bg1[j2-64]; }
        else              g_b3u[j-384] = badp[j-384];
    }
}

__global__ void k_split_A(const float* __restrict__ A0, const float* __restrict__ A1,
                          const float* __restrict__ A2, const float* __restrict__ A3) {
    int i = blockIdx.x * 256 + threadIdx.x;
    int z = i >> 20, r = i & 1048575;
    const float* A = (z == 0) ? A0 : (z == 1) ? A1 : (z == 2) ? A2 : A3;
    float v = A[r];
    bf16 h = __float2bfloat16(v);
    g_Ah[i] = h;
    g_Al[i] = __float2bfloat16(v - bf2f(h));
}

// ---------------- fused dilated conv + tem slice -> xe ----------------
__global__ __launch_bounds__(256) void k_xe(const float* __restrict__ x,
                                            const float* __restrict__ tem,
                                            const float* __restrict__ w,
                                            const float* __restrict__ bias) {
    __shared__ float pool[9376];
    float* xs = pool;
    float* ws = pool + 3072;
    float* bs = pool + 9312;
    int tid = threadIdx.x;
    int b = blockIdx.x >> 8, n0 = (blockIdx.x & 255) * 4;
    for (int i = tid; i < 64*96; i += 256) { int o = i / 96, kk = i % 96; ws[kk*65 + o] = w[i]; }
    if (tid < 64) bs[tid] = bias[tid];
    for (int i = tid; i < 3072; i += 256) {
        int nn = i / 768, r = i % 768, ci = r / 24, tt = r % 24;
        xs[(nn*32 + ci)*24 + tt] = x[((size_t)(b*32 + ci)*1024 + n0 + nn)*24 + tt];
    }
    __syncthreads();
    int co = tid & 63, nn = tid >> 6;
    float acc[20];
#pragma unroll
    for (int t = 0; t < 20; t++) acc[t] = bs[co];
    for (int ci = 0; ci < 32; ci++) {
        float w0 = ws[(ci*3+0)*65 + co], w1 = ws[(ci*3+1)*65 + co], w2 = ws[(ci*3+2)*65 + co];
        const float* xr = &xs[(nn*32 + ci)*24];
#pragma unroll
        for (int t = 0; t < 20; t++) acc[t] += w0*xr[t] + w1*xr[t+2] + w2*xr[t+4];
    }
    __syncthreads();
    float* sxe = pool;
#pragma unroll
    for (int t = 0; t < 20; t++) sxe[(nn*20 + t)*96 + co] = fmaxf(acc[t], 0.f);
    for (int i = tid; i < 2560; i += 256) {
        int nn2 = i / 640, r = i % 640, ci = r / 20, t = r % 20;
        sxe[(nn2*20 + t)*96 + 64 + ci] = tem[((size_t)(b*32 + ci)*1024 + n0 + nn2)*24 + 4 + t];
    }
    __syncthreads();
    if (tid < 160) {
        int half = tid / 80, rr = tid % 80;
        int nn2 = rr / 20, t = rr % 20;
        size_t J = (size_t)((b*1024 + n0 + nn2)*20 + t);
        bf16* dst = (half ? g_xel : g_xeh) + J*128;
        const float* srow = &sxe[rr*96];
        for (int cb = 0; cb < 128; cb += 8) {
            bf16 tmp[8];
#pragma unroll
            for (int u = 0; u < 8; u++) {
                float vv = (cb + u < 96) ? srow[cb + u] : 0.f;
                bf16 hv = __float2bfloat16(vv);
                tmp[u] = half ? __float2bfloat16(vv - bf2f(hv)) : hv;
            }
            *(uint4*)(dst + cb) = *(uint4*)tmp;
        }
    }
}

// ---------------- persistent multi-tile tensor-core GEMM ----------------
struct GemmArgs {
    const bf16 *ah, *al;
    const bf16 *wh, *wl;        // [K/64][N][64]
    const float* bias;
    float* outf;                // MODE 0
    bf16 *oh, *ol;              // MODE 1/2
    int opitch;
    float* outfin;              // MODE 3
};

template<int K_, int NN, int MODE>
__global__ __launch_bounds__(256) void k_gemm(GemmArgs p) {
    constexpr int NCH = K_ / 64;
    constexpr int WB  = NN * 128;
    constexpr int GT  = JPB * NCH;
    extern __shared__ char smem[];
    int tid = threadIdx.x, wid = tid >> 5, lane = tid & 31;
    size_t J0 = (size_t)blockIdx.x * (JPB*128);
    float* sh1f = (float*)(smem + 1024 + NCH*2*WB + 65536);   // MODE3 only

#ifdef TC_PATH
    uint32_t sb = smem_u32(smem);
    if (wid == 0) TC_ALLOC(sb, 512);
    if (tid == 0) { MBARRIER_INIT(sb+8, 1); MBARRIER_INIT(sb+16, 1); }
    __syncthreads();
    uint32_t tmem;
    asm volatile("ld.shared.b32 %0, [%1];" : "=r"(tmem) : "r"(sb));
    uint32_t wbase = sb + 1024;
    uint32_t abase = wbase + NCH*2*WB;

    // resident weights (all chunks, h+l)
    for (int i = tid; i < NCH*2*NN*8; i += 256) {
        int c = i / (2*NN*8), rem = i % (2*NN*8);
        int part = rem / (NN*8), e = rem % (NN*8);
        int r = e >> 3, c8 = e & 7;
        const bf16* src = (part ? p.wl : p.wh) + ((size_t)c*NN + r)*64 + c8*8;
        cpa16(wbase + (c*2+part)*WB + SWZ(r*128 + c8*16), src);
    }
    auto load_act = [&](int g, uint32_t st) {
        int tile = g / NCH, c = g % NCH;
        for (int i = tid; i < 2048; i += 256) {
            int part = i >> 10, e = i & 1023, r = e >> 3, c8 = e & 7;
            const bf16* src = (part ? p.al : p.ah) + (J0 + tile*128 + r)*K_ + c*64 + c8*8;
            cpa16(st + part*16384 + SWZ(r*128 + c8*16), src);
        }
    };
    load_act(0, abase);
    cpa_commit();

    int pending = -1;
    auto epilogue = [&](int tile) {
        int gl = tile*NCH + NCH - 1;
        MBAR_WAIT(sb + 8 + 8*(gl & 1), (gl >> 1) & 1);
        TC_FENCE_AFTER();
        int sub = wid & 3, grp = wid >> 2;
        int m = sub*32 + lane;
        size_t J = J0 + (size_t)tile*128 + m;
        uint32_t ta = tmem + (tile & 1)*256;
        if (MODE == 0) {
            uint32_t r[96];
            TC_LD_X32(r,      ta + grp*96);
            TC_LD_X32(r + 32, ta + grp*96 + 32);
            TC_LD_X32(r + 64, ta + grp*96 + 64);
            TC_WAIT_LD();
            size_t ob = J*192 + grp*96;
#pragma unroll
            for (int c = 0; c < 96; c += 4) {
                float4 v;
                v.x = __uint_as_float(r[c+0]) + p.bias[grp*96 + c + 0];
                v.y = __uint_as_float(r[c+1]) + p.bias[grp*96 + c + 1];
                v.z = __uint_as_float(r[c+2]) + p.bias[grp*96 + c + 2];
                v.w = __uint_as_float(r[c+3]) + p.bias[grp*96 + c + 3];
                *(float4*)(p.outf + ob + c) = v;
            }
        } else if (MODE == 1 || MODE == 2) {
            constexpr int NW = NN / 2;
            uint32_t r[NW];
#pragma unroll
            for (int i = 0; i < NW/32; i++) TC_LD_X32(r + i*32, ta + grp*NW + i*32);
            TC_WAIT_LD();
            size_t ob = J * p.opitch + grp*NW;
#pragma unroll
            for (int cb = 0; cb < NW; cb += 8) {
                bf16 th[8], tl[8];
#pragma unroll
                for (int u = 0; u < 8; u++) {
                    float v = fmaxf(__uint_as_float(r[cb+u]) + p.bias[grp*NW + cb + u], 0.f);
                    bf16 hv = __float2bfloat16(v);
                    th[u] = hv;
                    tl[u] = __float2bfloat16(v - bf2f(hv));
                }
                *(uint4*)(p.oh + ob + cb) = *(uint4*)th;
                *(uint4*)(p.ol + ob + cb) = *(uint4*)tl;
            }
        } else {
            uint32_t r[128];
            if (grp == 0) {
                TC_LD_X32(r,      ta);
                TC_LD_X32(r + 32, ta + 32);
                TC_LD_X32(r + 64, ta + 64);
                TC_LD_X32(r + 96, ta + 96);
            } else {
                TC_LD_X32(r,      ta + 128);
                TC_LD_X32(r + 32, ta + 160);
            }
            TC_WAIT_LD();
            if (grp == 1)
                for (int c = 0; c < 64; c++) sh1f[m*64 + c] = __uint_as_float(r[c]);
            __syncthreads();
            if (grp == 0) {
                float s0 = 0.f, s1 = 0.f;
                float uu[64];
#pragma unroll
                for (int c = 0; c < 64; c++) uu[c] = __uint_as_float(r[c]) + p.bias[c];
#pragma unroll
                for (int c = 0; c < 64; c++) {
                    s0 += uu[c] * __uint_as_float(r[64 + c]);
                    s1 += uu[c] * sh1f[m*64 + c];
                }
                float mx = fmaxf(s0, s1);
                float e0 = __expf(s0 - mx), e1 = __expf(s1 - mx);
                float inv = 1.f / (e0 + e1);
                float a0 = e0*inv, a1 = e1*inv;
                int b = (int)(J / 20480), rr = (int)(J % 20480), n = rr / 20, t = rr % 20;
                for (int c = 0; c < 64; c++)
                    p.outfin[((size_t)(b*64 + c)*1024 + n)*20 + t] =
                        a0*__uint_as_float(r[64 + c]) + a1*sh1f[m*64 + c];
            }
            __syncthreads();
        }
    };

    for (int g = 0; g < GT; g++) {
        int buf = g & 1;
        if (g + 1 < GT) {
            if (g >= 1) MBAR_WAIT(sb + 8 + 8*(1 - buf), ((g - 1) >> 1) & 1);
            load_act(g + 1, abase + (1 - buf)*32768);
            cpa_commit();
            cpa_wait1();
        } else {
            cpa_wait0();
        }
        __syncthreads();
        if (wid == 0) {
            asm volatile("fence.proxy.async.shared::cta;" ::: "memory");
            if (elect1()) {
                int c = g % NCH, tile = g / NCH;
                uint32_t s0 = abase + buf*32768;
                uint64_t ah = make_desc(s0);
                uint64_t al = make_desc(s0 + 16384);
                uint64_t wh = make_desc(wbase + (c*2)*WB);
                uint64_t wl = make_desc(wbase + (c*2+1)*WB);
                uint32_t d = tmem + (tile & 1)*256;
#pragma unroll
                for (int ks = 0; ks < 4; ks++) {
                    mma_bf(d, ah + 2*ks, wh + 2*ks, IDESC(NN), !(c == 0 && ks == 0));
                    mma_bf(d, ah + 2*ks, wl + 2*ks, IDESC(NN), true);
                    mma_bf(d, al + 2*ks, wh + 2*ks, IDESC(NN), true);
                }
                TC_COMMIT(sb + 8 + 8*buf);
            }
        }
        if (pending >= 0) { epilogue(pending); pending = -1; }
        if (g % NCH == NCH - 1) pending = g / NCH;
    }
    epilogue(pending);
    __syncthreads();
    if (tid == 0) { MBARRIER_INVAL(sb+8); MBARRIER_INVAL(sb+16); }
    if (wid == 0) { TC_RELINQ(); TC_DEALLOC(tmem, 512); }
#else
    for (int tile = 0; tile < JPB; tile++) {
        for (int m = tid; m < 128; m += 256) {
            size_t J = J0 + (size_t)tile*128 + m;
            if (MODE == 3) {
                float uu[64], h0[64], h1[64];
                for (int n = 0; n < 192; n++) {
                    float acc = 0.f;
                    for (int k = 0; k < K_; k++) {
                        float av = bf2f(p.ah[J*K_ + k]) + bf2f(p.al[J*K_ + k]);
                        size_t wi = ((size_t)(k >> 6)*NN + n)*64 + (k & 63);
                        acc += av * (bf2f(p.wh[wi]) + bf2f(p.wl[wi]));
                    }
                    if (n < 64) uu[n] = acc + p.bias[n];
                    else if (n < 128) h0[n-64] = acc;
                    else h1[n-128] = acc;
                }
                float s0 = 0.f, s1 = 0.f;
                for (int c = 0; c < 64; c++) { s0 += uu[c]*h0[c]; s1 += uu[c]*h1[c]; }
                float mx = fmaxf(s0, s1);
                float e0 = __expf(s0-mx), e1 = __expf(s1-mx), inv = 1.f/(e0+e1);
                int b = (int)(J/20480), rr = (int)(J%20480), n2 = rr/20, t = rr%20;
                for (int c = 0; c < 64; c++)
                    p.outfin[((size_t)(b*64+c)*1024+n2)*20+t] = (e0*h0[c]+e1*h1[c])*inv;
            } else {
                for (int n = 0; n < NN; n++) {
                    float acc = 0.f;
                    for (int k = 0; k < K_; k++) {
                        float av = bf2f(p.ah[J*K_ + k]) + bf2f(p.al[J*K_ + k]);
                        size_t wi = ((size_t)(k >> 6)*NN + n)*64 + (k & 63);
                        acc += av * (bf2f(p.wh[wi]) + bf2f(p.wl[wi]));
                    }
                    if (MODE == 0) p.outf[J*192 + n] = acc + p.bias[n];
                    else {
                        float v = fmaxf(acc + p.bias[n], 0.f);
                        bf16 hv = __float2bfloat16(v);
                        p.oh[J*p.opitch + n] = hv;
                        p.ol[J*p.opitch + n] = __float2bfloat16(v - bf2f(hv));
                    }
                }
            }
        }
    }
#endif
}

// ---------------- attention ----------------
__global__ __launch_bounds__(256) void k_attn() {
    __shared__ float sbuf[8][880];
    int warp = threadIdx.x >> 5, lane = threadIdx.x & 31;
    int g = blockIdx.x * 8 + warp;
    int b = g >> 13, h = (g >> 10) & 7, n = g & 1023;
    float* q = sbuf[warp];
    float* k = q + 160;
    float* v = k + 160;
    float* S = v + 160;
    size_t Jb = (size_t)(b*1024 + n)*20;
    for (int idx = lane; idx < 160; idx += 32) {
        int d = idx / 20, t = idx % 20;
        size_t row = (Jb + t)*192 + h*8 + d;
        q[idx] = g_qkvJ[row];
        k[idx] = g_qkvJ[row + 64];
        v[idx] = g_qkvJ[row + 128];
    }
    __syncwarp();
    for (int idx = lane; idx < 400; idx += 32) {
        int t = idx / 20, s = idx % 20;
        if (s <= t) {
            float acc = 0.f;
#pragma unroll
            for (int d = 0; d < 8; d++) acc += q[d*20 + t] * k[d*20 + s];
            S[idx] = acc * 0.35355339059327373f;
        }
    }
    __syncwarp();
    if (lane < 20) {
        int t = lane;
        float mx = -1e30f;
        for (int s = 0; s <= t; s++) mx = fmaxf(mx, S[t*20 + s]);
        float sum = 0.f;
        for (int s = 0; s <= t; s++) { float e = __expf(S[t*20 + s] - mx); S[t*20 + s] = e; sum += e; }
        float inv = 1.f / sum;
        for (int s = 0; s <= t; s++) S[t*20 + s] *= inv;
    }
    __syncwarp();
    for (int idx = lane; idx < 160; idx += 32) {
        int d = idx / 20, t = idx % 20;
        float acc = 0.f;
        for (int s = 0; s <= t; s++) acc += S[t*20 + s] * v[d*20 + s];
        q[idx] = acc;
    }
    __syncwarp();
    if (lane < 20) {
        int t = lane;
        bf16 th[8], tl[8];
#pragma unroll
        for (int d = 0; d < 8; d++) {
            float vv = q[d*20 + t];
            bf16 hv = __float2bfloat16(vv);
            th[d] = hv;
            tl[d] = __float2bfloat16(vv - bf2f(hv));
        }
        size_t ob = (Jb + t)*64 + h*8;
        *(uint4*)(g_atth + ob) = *(uint4*)th;
        *(uint4*)(g_attl + ob) = *(uint4*)tl;
    }
}

// ---------------- transpose x2 -> xt[(b,t,c)][n] ----------------
__global__ __launch_bounds__(256) void k_xt() {
    __shared__ bf16 th[64][72], tl[64][72];
    int tid = threadIdx.x;
    int b = blockIdx.x, t = blockIdx.y, n0 = blockIdx.z * 64;
    for (int i = tid; i < 512; i += 256) {
        int r = i >> 3, c8 = i & 7;
        size_t src = ((size_t)(b*1024 + n0 + r)*20 + t)*320 + c8*8;
        *(uint4*)(&th[r][c8*8]) = *(const uint4*)(g_hch + src);
        *(uint4*)(&tl[r][c8*8]) = *(const uint4*)(g_hcl + src);
    }
    __syncthreads();
    for (int i = tid; i < 512; i += 256) {
        int c = i >> 3, n8 = i & 7;
        bf16 vh[8], vl[8];
#pragma unroll
        for (int u = 0; u < 8; u++) { vh[u] = th[n8*8 + u][c]; vl[u] = tl[n8*8 + u][c]; }
        size_t dst = (size_t)(b*1280 + t*64 + c)*1024 + n0 + n8*8;
        *(uint4*)(g_xth + dst) = *(uint4*)vh;
        *(uint4*)(g_xtl + dst) = *(uint4*)vl;
    }
}

// ---------------- nconv ----------------
#define NSTG 98304
#define NSMEM (1024 + 2*NSTG)
__device__ __forceinline__ void nc_load(int k0, uint32_t st,
                                        const bf16* Ah, const bf16* Al,
                                        int m0, int j0, int tid) {
    for (int g = tid; g < 6144; g += 256) {
        uint32_t dst; const void* src;
        if (g < 2048) {
            int part = g >> 10, e = g & 1023, r = e >> 3, c8 = e & 7;
            src = (part ? Al : Ah) + (size_t)(m0 + r)*1024 + k0 + c8*8;
            dst = st + part*16384 + SWZ(r*128 + c8*16);
        } else {
            int j = g - 2048;
            int part = j >> 11, e = j & 2047, r = e >> 3, c8 = e & 7;
            src = (part ? g_xtl : g_xth) + (size_t)(j0 + r)*1024 + k0 + c8*8;
            dst = st + 32768 + part*32768 + SWZ(r*128 + c8*16);
        }
        cpa16(dst, src);
    }
}

__global__ __launch_bounds__(256) void k_nconv_tc() {
    extern __shared__ char smem[];
    int tid = threadIdx.x, wid = tid >> 5, lane = tid & 31;
    int j0 = blockIdx.x * 256, m0 = blockIdx.y * 128, z = blockIdx.z;
    const bf16* Ah = g_Ah + (size_t)z*1024*1024;
    const bf16* Al = g_Al + (size_t)z*1024*1024;
    float* Dt = (float*)(smem + 1024);

#ifdef TC_PATH
    uint32_t sb = smem_u32(smem);
    if (wid == 0) TC_ALLOC(sb, 256);
    if (tid == 0) { MBARRIER_INIT(sb+8, 1); MBARRIER_INIT(sb+16, 1); }
    __syncthreads();
    uint32_t tmem;
    asm volatile("ld.shared.b32 %0, [%1];" : "=r"(tmem) : "r"(sb));
    uint32_t bufb = sb + 1024;

    nc_load(0, bufb, Ah, Al, m0, j0, tid);
    cpa_commit();
    int ph0 = 0, ph1 = 0;
    for (int ch = 0; ch < 16; ch++) {
        int buf = ch & 1;
        if (ch + 1 < 16) {
            int nb = 1 - buf;
            if (ch >= 1) {
                MBAR_WAIT(sb + 8 + 8*nb, (nb == 0) ? ph0 : ph1);
                if (nb == 0) ph0 ^= 1; else ph1 ^= 1;
            }
            nc_load((ch+1)*64, bufb + NSTG*nb, Ah, Al, m0, j0, tid);
            cpa_commit();
            cpa_wait1();
        } else {
            cpa_wait0();
        }
        __syncthreads();
        if (wid == 0) {
            asm volatile("fence.proxy.async.shared::cta;" ::: "memory");
            if (elect1()) {
                uint32_t s0 = bufb + NSTG*buf;
                uint64_t ah = make_desc(s0);
                uint64_t al = make_desc(s0 + 16384);
                uint64_t xh = make_desc(s0 + 32768);
                uint64_t xl = make_desc(s0 + 65536);
#pragma unroll
                for (int ks = 0; ks < 4; ks++) {
                    mma_bf(tmem, ah + 2*ks, xh + 2*ks, IDESC(256), !(ch == 0 && ks == 0));
                    mma_bf(tmem, ah + 2*ks, xl + 2*ks, IDESC(256), true);
                    mma_bf(tmem, al + 2*ks, xh + 2*ks, IDESC(256), true);
                }
                TC_COMMIT(sb + 8 + 8*buf);
            }
        }
    }
    MBAR_WAIT(sb + 16, ph1);
    TC_FENCE_AFTER();
    __syncthreads();
    {
        int sub = wid & 3, hf = wid >> 2;
        int m = sub*32 + lane;
#pragma unroll
        for (int i = 0; i < 4; i++) {
            uint32_t r[32];
            int cb = hf*128 + i*32;
            TC_LD_X32(r, tmem + cb);
            TC_WAIT_LD();
#pragma unroll
            for (int c = 0; c < 32; c++) Dt[(cb + c)*129 + m] = __uint_as_float(r[c]);
        }
    }
    __syncthreads();
    if (tid == 0) { MBARRIER_INVAL(sb+8); MBARRIER_INVAL(sb+16); }
    if (wid == 0) { TC_RELINQ(); TC_DEALLOC(tmem, 256); }
    __syncthreads();
#else
    for (int idx = tid; idx < 128*256; idx += 256) {
        int m = idx >> 8, jl = idx & 255;
        float acc = 0.f;
        for (int kk = 0; kk < 1024; kk++) {
            float av = bf2f(Ah[(size_t)(m0+m)*1024 + kk]) + bf2f(Al[(size_t)(m0+m)*1024 + kk]);
            float xv = bf2f(g_xth[(size_t)(j0+jl)*1024 + kk]) + bf2f(g_xtl[(size_t)(j0+jl)*1024 + kk]);
            acc += av * xv;
        }
        Dt[jl*129 + m] = acc;
    }
    __syncthreads();
#endif

    int b = j0 / 1280, t0 = (j0 % 1280) / 64;
    for (int task = tid; task < 512; task += 256) {
        int w = task >> 2, tq = task & 3;
        size_t J = (size_t)(b*1024 + m0 + w)*20 + t0 + tq;
        size_t ob = J*320 + 64 + z*64;
        for (int cb = 0; cb < 64; cb += 8) {
            bf16 th[8], tl[8];
#pragma unroll
            for (int u = 0; u < 8; u++) {
                float vv = Dt[(tq*64 + cb + u)*129 + w];
                bf16 hv = __float2bfloat16(vv);
                th[u] = hv;
                tl[u] = __float2bfloat16(vv - bf2f(hv));
            }
            *(uint4*)(g_hch + ob + cb) = *(uint4*)th;
            *(uint4*)(g_hcl + ob + cb) = *(uint4*)tl;
        }
    }
}

// ---------------- launch ----------------
extern "C" void kernel_launch(void* const* d_in, const int* in_sizes, int n_in,
                              void* d_out, int out_size) {
    const float* x    = (const float*)d_in[0];
    const float* tem  = (const float*)d_in[1];
    float* out = (float*)d_out;

    GemmArgs base = {};
    float *p_qkvJ, *p_bqkv, *p_bo, *p_bh, *p_b3u;
    cudaGetSymbolAddress((void**)&p_qkvJ, g_qkvJ);
    cudaGetSymbolAddress((void**)&p_bqkv, g_bqkv);
    cudaGetSymbolAddress((void**)&p_bo,   g_bo);
    cudaGetSymbolAddress((void**)&p_bh,   g_bh);
    cudaGetSymbolAddress((void**)&p_b3u,  g_b3u);
    bf16 *p_xeh, *p_xel, *p_atth, *p_attl, *p_hch, *p_hcl, *p_h01h, *p_h01l;
    bf16 *p_wqkvh, *p_wqkvl, *p_woh, *p_wol, *p_wgh, *p_wgl, *p_w3h, *p_w3l;
    cudaGetSymbolAddress((void**)&p_xeh, g_xeh);   cudaGetSymbolAddress((void**)&p_xel, g_xel);
    cudaGetSymbolAddress((void**)&p_atth, g_atth); cudaGetSymbolAddress((void**)&p_attl, g_attl);
    cudaGetSymbolAddress((void**)&p_hch, g_hch);   cudaGetSymbolAddress((void**)&p_hcl, g_hcl);
    cudaGetSymbolAddress((void**)&p_h01h, g_h01h); cudaGetSymbolAddress((void**)&p_h01l, g_h01l);
    cudaGetSymbolAddress((void**)&p_wqkvh, g_wqkvh); cudaGetSymbolAddress((void**)&p_wqkvl, g_wqkvl);
    cudaGetSymbolAddress((void**)&p_woh, g_woh);   cudaGetSymbolAddress((void**)&p_wol, g_wol);
    cudaGetSymbolAddress((void**)&p_wgh, g_wgh);   cudaGetSymbolAddress((void**)&p_wgl, g_wgl);
    cudaGetSymbolAddress((void**)&p_w3h, g_w3h);   cudaGetSymbolAddress((void**)&p_w3l, g_w3l);

    const int S_QKV = 1024 + 2*2*192*128 + 65536;            // 164864
    const int S_WO  = 1024 + 1*2*64*128 + 65536;             // 82944
    const int S_H   = 1024 + 5*2*128*128 + 65536;            // 230400
    const int S_W3  = 1024 + 2*2*192*128 + 65536 + 32768;    // 197632
    cudaFuncSetAttribute(k_gemm<128,192,0>, cudaFuncAttributeMaxDynamicSharedMemorySize, S_QKV);
    cudaFuncSetAttribute(k_gemm<64,64,1>,   cudaFuncAttributeMaxDynamicSharedMemorySize, S_WO);
    cudaFuncSetAttribute(k_gemm<320,128,2>, cudaFuncAttributeMaxDynamicSharedMemorySize, S_H);
    cudaFuncSetAttribute(k_gemm<128,192,3>, cudaFuncAttributeMaxDynamicSharedMemorySize, S_W3);
    cudaFuncSetAttribute(k_nconv_tc,        cudaFuncAttributeMaxDynamicSharedMemorySize, NSMEM);

    k_wsplit<<<370, 256>>>(
        (const float*)d_in[8],  (const float*)d_in[9],
        (const float*)d_in[10], (const float*)d_in[11],
        (const float*)d_in[12], (const float*)d_in[13],
        (const float*)d_in[14], (const float*)d_in[15],
        (const float*)d_in[16], (const float*)d_in[17],
        (const float*)d_in[18], (const float*)d_in[19],
        (const float*)d_in[20], (const float*)d_in[21],
        (const float*)d_in[22]);
    k_split_A<<<16384, 256>>>((const float*)d_in[2], (const float*)d_in[3],
                              (const float*)d_in[4], (const float*)d_in[5]);
    k_xe<<<4096, 256>>>(x, tem, (const float*)d_in[6], (const float*)d_in[7]);

    GemmArgs a = base;
    a.ah = p_xeh; a.al = p_xel; a.wh = p_wqkvh; a.wl = p_wqkvl;
    a.bias = p_bqkv; a.outf = p_qkvJ;
    k_gemm<128,192,0><<<GB_, 256, S_QKV>>>(a);

    k_attn<<<16384, 256>>>();

    a = base;
    a.ah = p_atth; a.al = p_attl; a.wh = p_woh; a.wl = p_wol;
    a.bias = p_bo; a.oh = p_hch; a.ol = p_hcl; a.opitch = 320;
    k_gemm<64,64,1><<<GB_, 256, S_WO>>>(a);

    k_xt<<<dim3(16, 20, 16), 256>>>();
    k_nconv_tc<<<dim3(80, 8, 4), 256, NSMEM>>>();

    a = base;
    a.ah = p_hch; a.al = p_hcl; a.wh = p_wgh; a.wl = p_wgl;
    a.bias = p_bh; a.oh = p_h01h; a.ol = p_h01l; a.opitch = 128;
    k_gemm<320,128,2><<<GB_, 256, S_H>>>(a);

    a = base;
    a.ah = p_h01h; a.al = p_h01l; a.wh = p_w3h; a.wl = p_w3l;
    a.bias = p_b3u; a.outfin = out;
    k_gemm<128,192,3><<<GB_, 256, S_W3>>>(a);
}

// round 7
// speedup vs baseline: 1.7688x; 1.2287x over previous
#include <cuda_runtime.h>
#include <cuda_bf16.h>
#include <cstdint>

#define B_   16
#define N_   1024
#define TO_  20
#define JT_  327680
#define JPB  8
#define GB_  320

#if defined(__CUDA_ARCH_FEAT_SM103_ALL) || defined(__CUDA_ARCH_FEAT_SM100_ALL)
#define TC_PATH 1
#endif

typedef __nv_bfloat16 bf16;

__device__ float g_qkvJ[(size_t)JT_*192];
__device__ __align__(256) bf16 g_xeh[(size_t)JT_*128], g_xel[(size_t)JT_*128];
__device__ __align__(256) bf16 g_atth[(size_t)JT_*64], g_attl[(size_t)JT_*64];
__device__ __align__(256) bf16 g_hch[(size_t)JT_*320], g_hcl[(size_t)JT_*320];
__device__ __align__(256) bf16 g_xth[(size_t)20480*1024], g_xtl[(size_t)20480*1024];
__device__ __align__(256) bf16 g_h01h[(size_t)JT_*128], g_h01l[(size_t)JT_*128];
__device__ __align__(256) bf16 g_Ah[4*1024*1024], g_Al[4*1024*1024];
__device__ __align__(256) bf16 g_wqkvh[24576], g_wqkvl[24576];
__device__ __align__(256) bf16 g_woh[4096],   g_wol[4096];
__device__ __align__(256) bf16 g_wgh[40960],  g_wgl[40960];
__device__ __align__(256) bf16 g_w3h[24576],  g_w3l[24576];
__device__ float g_bqkv[192], g_bo[64], g_bh[128], g_b3u[64];

__device__ __forceinline__ float bf2f(bf16 v) { return __bfloat162float(v); }
__device__ __forceinline__ uint32_t smem_u32(const void* p) {
    uint32_t a;
    asm("{ .reg .u64 t; cvta.to.shared.u64 t, %1; cvt.u32.u64 %0, t; }" : "=r"(a) : "l"(p));
    return a;
}
__device__ __forceinline__ void cpa16(uint32_t dst, const void* src) {
    asm volatile("cp.async.cg.shared.global [%0], [%1], 16;" :: "r"(dst), "l"(src));
}
__device__ __forceinline__ void cpa_commit() { asm volatile("cp.async.commit_group;" ::: "memory"); }
__device__ __forceinline__ void cpa_wait1()  { asm volatile("cp.async.wait_group 1;" ::: "memory"); }
__device__ __forceinline__ void cpa_wait0()  { asm volatile("cp.async.wait_group 0;" ::: "memory"); }
#define SWZ(o) ((o) ^ (((o) >> 3) & 0x70))

#ifdef TC_PATH
__device__ __forceinline__ uint32_t elect1() {
    uint32_t p;
    asm volatile("{\n\t.reg .pred p;\n\telect.sync _|p, 0xFFFFFFFF;\n\tselp.b32 %0, 1, 0, p;\n\t}" : "=r"(p));
    return p;
}
#define MBARRIER_INIT(addr, cnt) \
    asm volatile("mbarrier.init.shared.b64 [%0], %1;" :: "r"(addr), "r"(cnt) : "memory")
#define MBARRIER_INVAL(addr) \
    asm volatile("mbarrier.inval.shared.b64 [%0];" :: "r"(addr) : "memory")
#define MBAR_WAIT(mb, par) do { \
    uint32_t _m = (uint32_t)(mb), _p = (uint32_t)(par), _d; \
    asm volatile("{\n\t.reg .pred p;\n\t" \
        "mbarrier.try_wait.parity.acquire.cta.shared::cta.b64 p, [%1], %2;\n\t" \
        "selp.b32 %0, 1, 0, p;\n\t}" : "=r"(_d) : "r"(_m), "r"(_p) : "memory"); \
    if (!_d) { \
        asm volatile("{\n\t.reg .pred P1;\n\t" \
            "WL_%=:\n\t" \
            "mbarrier.try_wait.parity.acquire.cta.shared::cta.b64 P1, [%0], %1, 0x989680;\n\t" \
            "@P1 bra.uni WD_%=;\n\tbra.uni WL_%=;\n\tWD_%=:\n\t}" \
            :: "r"(_m), "r"(_p) : "memory"); \
    } \
} while(0)
#define TC_ALLOC(saddr, n) \
    asm volatile("tcgen05.alloc.cta_group::1.sync.aligned.shared::cta.b32 [%0], %1;" \
        :: "r"((uint32_t)(saddr)), "r"((uint32_t)(n)) : "memory")
#define TC_DEALLOC(tmem, n) \
    asm volatile("tcgen05.dealloc.cta_group::1.sync.aligned.b32 %0, %1;" :: "r"(tmem), "r"((uint32_t)(n)))
#define TC_RELINQ() asm volatile("tcgen05.relinquish_alloc_permit.cta_group::1.sync.aligned;")
#define TC_COMMIT(mbar) \
    asm volatile("tcgen05.commit.cta_group::1.mbarrier::arrive::one.shared::cluster.b64 [%0];" \
        :: "r"((uint32_t)(mbar)) : "memory")
#define TC_FENCE_AFTER() asm volatile("tcgen05.fence::after_thread_sync;" ::: "memory")
#define TC_WAIT_LD() asm volatile("tcgen05.wait::ld.sync.aligned;" ::: "memory")
#define TC_LD_X32(r, ta) \
    asm volatile("tcgen05.ld.sync.aligned.32x32b.x32.b32 " \
        "{%0, %1, %2, %3, %4, %5, %6, %7, %8, %9, %10, %11, %12, %13, %14, %15, " \
        " %16, %17, %18, %19, %20, %21, %22, %23, %24, %25, %26, %27, %28, %29, %30, %31}, [%32];" \
        : "=r"((r)[0]),  "=r"((r)[1]),  "=r"((r)[2]),  "=r"((r)[3]), \
          "=r"((r)[4]),  "=r"((r)[5]),  "=r"((r)[6]),  "=r"((r)[7]), \
          "=r"((r)[8]),  "=r"((r)[9]),  "=r"((r)[10]), "=r"((r)[11]), \
          "=r"((r)[12]), "=r"((r)[13]), "=r"((r)[14]), "=r"((r)[15]), \
          "=r"((r)[16]), "=r"((r)[17]), "=r"((r)[18]), "=r"((r)[19]), \
          "=r"((r)[20]), "=r"((r)[21]), "=r"((r)[22]), "=r"((r)[23]), \
          "=r"((r)[24]), "=r"((r)[25]), "=r"((r)[26]), "=r"((r)[27]), \
          "=r"((r)[28]), "=r"((r)[29]), "=r"((r)[30]), "=r"((r)[31]) \
        : "r"(ta))
__device__ __forceinline__ uint64_t make_desc(uint32_t addr) {
    return 0x4000404000010000ULL | (uint64_t)((addr >> 4) & 0x3FFF);
}
__device__ __forceinline__ void mma_bf(uint32_t d, uint64_t a, uint64_t b, uint32_t idesc, bool acc) {
    uint32_t en = acc ? 1u : 0u;
    asm volatile("{\n\t.reg .pred p;\n\tsetp.ne.u32 p, %5, 0;\n\t"
        "tcgen05.mma.cta_group::1.kind::f16 [%0], %1, %2, %3, {%4, %4, %4, %4}, p;\n\t}"
        :: "r"(d), "l"(a), "l"(b), "r"(idesc), "r"(0u), "r"(en) : "memory");
}
#define IDESC(n) (0x8000490u | (((n)/8) << 17))
#endif

// ---------------- weight split/pack ----------------
__global__ void k_wsplit(const float* __restrict__ wq, const float* __restrict__ bq,
                         const float* __restrict__ wk, const float* __restrict__ bk,
                         const float* __restrict__ wv, const float* __restrict__ bv,
                         const float* __restrict__ wo, const float* __restrict__ bo,
                         const float* __restrict__ wg0, const float* __restrict__ bg0,
                         const float* __restrict__ wg1, const float* __restrict__ bg1,
                         const float* __restrict__ wadp, const float* __restrict__ badp,
                         const float* __restrict__ w0f) {
    int i = blockIdx.x * 256 + threadIdx.x;
    if (i < 24576) {
        int c = i / 12288, rem = i % 12288, r = rem / 64, k = rem & 63, col = c*64 + k;
        int s = r / 64, rr = r % 64;
        const float* W = (s == 0) ? wq : (s == 1) ? wk : wv;
        float v = (col < 96) ? W[rr*96 + col] : 0.f;
        bf16 h = __float2bfloat16(v);
        g_wqkvh[i] = h; g_wqkvl[i] = __float2bfloat16(v - bf2f(h));
    } else if (i < 28672) {
        int j = i - 24576;
        float v = wo[j];
        bf16 h = __float2bfloat16(v);
        g_woh[j] = h; g_wol[j] = __float2bfloat16(v - bf2f(h));
    } else if (i < 69632) {
        int j = i - 28672;
        int c = j / 8192, rem = j % 8192, r = rem / 64, k = rem & 63, col = c*64 + k;
        float v;
        if (r < 64) v = (col < 192) ? wg0[r*192 + col] : 0.f;
        else {
            int rr = r - 64;
            if (col < 64) v = wg1[rr*192 + col];
            else if (col >= 192) v = wg1[rr*192 + col - 128];
            else v = 0.f;
        }
        bf16 h = __float2bfloat16(v);
        g_wgh[j] = h; g_wgl[j] = __float2bfloat16(v - bf2f(h));
    } else if (i < 94208) {
        int j = i - 69632;
        int c = j / 12288, rem = j % 12288, r = rem / 64, k = rem & 63, col = c*64 + k;
        float v;
        if (r < 64)       v = wadp[r*128 + col];
        else if (r < 128) v = (col < 64) ? w0f[(r-64)*64 + col] : 0.f;
        else              v = (col >= 64) ? w0f[(r-128)*64 + col - 64] : 0.f;
        bf16 h = __float2bfloat16(v);
        g_w3h[j] = h; g_w3l[j] = __float2bfloat16(v - bf2f(h));
    } else if (i < 94656) {
        int j = i - 94208;
        if (j < 192)      g_bqkv[j] = (j < 64) ? bq[j] : (j < 128) ? bk[j-64] : bv[j-128];
        else if (j < 256) g_bo[j-192] = bo[j-192];
        else if (j < 384) { int j2 = j-256; g_bh[j2] = (j2 < 64) ? bg0[j2] : bg1[j2-64]; }
        else              g_b3u[j-384] = badp[j-384];
    }
}

__global__ void k_split_A(const float* __restrict__ A0, const float* __restrict__ A1,
                          const float* __restrict__ A2, const float* __restrict__ A3) {
    int i = blockIdx.x * 256 + threadIdx.x;
    int z = i >> 20, r = i & 1048575;
    const float* A = (z == 0) ? A0 : (z == 1) ? A1 : (z == 2) ? A2 : A3;
    float v = A[r];
    bf16 h = __float2bfloat16(v);
    g_Ah[i] = h;
    g_Al[i] = __float2bfloat16(v - bf2f(h));
}

// ---------------- fused dilated conv + tem slice -> xe ----------------
__global__ __launch_bounds__(256) void k_xe(const float* __restrict__ x,
                                            const float* __restrict__ tem,
                                            const float* __restrict__ w,
                                            const float* __restrict__ bias) {
    __shared__ float pool[9376];
    float* xs = pool;
    float* ws = pool + 3072;
    float* bs = pool + 9312;
    int tid = threadIdx.x;
    int b = blockIdx.x >> 8, n0 = (blockIdx.x & 255) * 4;
    for (int i = tid; i < 64*96; i += 256) { int o = i / 96, kk = i % 96; ws[kk*65 + o] = w[i]; }
    if (tid < 64) bs[tid] = bias[tid];
    for (int i = tid; i < 3072; i += 256) {
        int nn = i / 768, r = i % 768, ci = r / 24, tt = r % 24;
        xs[(nn*32 + ci)*24 + tt] = x[((size_t)(b*32 + ci)*1024 + n0 + nn)*24 + tt];
    }
    __syncthreads();
    int co = tid & 63, nn = tid >> 6;
    float acc[20];
#pragma unroll
    for (int t = 0; t < 20; t++) acc[t] = bs[co];
    for (int ci = 0; ci < 32; ci++) {
        float w0 = ws[(ci*3+0)*65 + co], w1 = ws[(ci*3+1)*65 + co], w2 = ws[(ci*3+2)*65 + co];
        const float* xr = &xs[(nn*32 + ci)*24];
#pragma unroll
        for (int t = 0; t < 20; t++) acc[t] += w0*xr[t] + w1*xr[t+2] + w2*xr[t+4];
    }
    __syncthreads();
    float* sxe = pool;
#pragma unroll
    for (int t = 0; t < 20; t++) sxe[(nn*20 + t)*96 + co] = fmaxf(acc[t], 0.f);
    for (int i = tid; i < 2560; i += 256) {
        int nn2 = i / 640, r = i % 640, ci = r / 20, t = r % 20;
        sxe[(nn2*20 + t)*96 + 64 + ci] = tem[((size_t)(b*32 + ci)*1024 + n0 + nn2)*24 + 4 + t];
    }
    __syncthreads();
    // coalesced split-bf16 write: 80 rows x 128 cols -> 256B runs, 16 lanes/run
    for (int idx = tid; idx < 2560; idx += 256) {
        int half = idx >= 1280;
        int e = half ? idx - 1280 : idx;
        int rr = e >> 4, o = e & 15;                 // row, 16B slot (8 bf16)
        int nn2 = rr / 20, t = rr % 20;
        size_t J = (size_t)((b*1024 + n0 + nn2)*20 + t);
        const float* srow = &sxe[rr*96];
        bf16 tmp[8];
#pragma unroll
        for (int u = 0; u < 8; u++) {
            int c = o*8 + u;
            float vv = (c < 96) ? srow[c] : 0.f;
            bf16 hv = __float2bfloat16(vv);
            tmp[u] = half ? __float2bfloat16(vv - bf2f(hv)) : hv;
        }
        *(uint4*)(((half ? g_xel : g_xeh) + J*128) + o*8) = *(uint4*)tmp;
    }
}

// ---------------- persistent multi-tile tensor-core GEMM ----------------
struct GemmArgs {
    const bf16 *ah, *al;
    const bf16 *wh, *wl;        // [K/64][N][64]
    const float* bias;
    float* outf;                // MODE 0
    bf16 *oh, *ol;              // MODE 1/2
    int opitch;
    float* outfin;              // MODE 3
};

template<int K_, int NN, int MODE>
__global__ __launch_bounds__(256) void k_gemm(GemmArgs p) {
    constexpr int NCH = K_ / 64;
    constexpr int WB  = NN * 128;
    constexpr int STG_ = 32768 + 2*WB;
    constexpr int GT  = JPB * NCH;
    extern __shared__ char smem[];
    int tid = threadIdx.x, wid = tid >> 5, lane = tid & 31;
    size_t J0 = (size_t)blockIdx.x * (JPB*128);
    float* Dt = (float*)(smem + 1024 + 2*STG_);      // [128][72] or sfin [64][132]

#ifdef TC_PATH
    uint32_t sb = smem_u32(smem);
    if (wid == 0) TC_ALLOC(sb, 512);
    if (tid == 0) { MBARRIER_INIT(sb+8, 1); MBARRIER_INIT(sb+16, 1); }
    __syncthreads();
    uint32_t tmem;
    asm volatile("ld.shared.b32 %0, [%1];" : "=r"(tmem) : "r"(sb));
    uint32_t abase = sb + 1024;

    auto load_stage = [&](int g, uint32_t st) {
        int tile = g / NCH, c = g % NCH;
        for (int i = tid; i < 2048 + 2*NN*8; i += 256) {
            uint32_t dst; const void* src;
            if (i < 2048) {
                int part = i >> 10, e = i & 1023, r = e >> 3, c8 = e & 7;
                src = (part ? p.al : p.ah) + (J0 + tile*128 + r)*K_ + c*64 + c8*8;
                dst = st + part*16384 + SWZ(r*128 + c8*16);
            } else {
                int j = i - 2048;
                int part = (j >= NN*8);
                int e = part ? j - NN*8 : j;
                int r = e >> 3, c8 = e & 7;
                src = (part ? p.wl : p.wh) + ((size_t)c*NN + r)*64 + c8*8;
                dst = st + 32768 + part*WB + SWZ(r*128 + c8*16);
            }
            cpa16(dst, src);
        }
    };
    load_stage(0, abase);
    cpa_commit();

    int pending = -1;
    int sub = wid & 3, grp = wid >> 2;
    int m = sub*32 + lane;

    auto epilogue = [&](int tile) {
        int gl = tile*NCH + NCH - 1;
        MBAR_WAIT(sb + 8 + 8*(gl & 1), (gl >> 1) & 1);
        TC_FENCE_AFTER();
        size_t J0t = J0 + (size_t)tile*128;
        uint32_t ta = tmem + (tile & 1)*256;
        if (MODE != 3) {
#pragma unroll
            for (int pp = 0; pp < NN/64; pp++) {
                uint32_t r[32];
                TC_LD_X32(r, ta + pp*64 + grp*32);
                TC_WAIT_LD();
#pragma unroll
                for (int c = 0; c < 32; c++) Dt[m*72 + grp*32 + c] = __uint_as_float(r[c]);
                __syncthreads();
                if (MODE == 0) {
                    for (int idx = tid; idx < 2048; idx += 256) {
                        int rr = idx >> 4, o = idx & 15;
                        float4 v;
                        v.x = Dt[rr*72 + o*4 + 0] + p.bias[pp*64 + o*4 + 0];
                        v.y = Dt[rr*72 + o*4 + 1] + p.bias[pp*64 + o*4 + 1];
                        v.z = Dt[rr*72 + o*4 + 2] + p.bias[pp*64 + o*4 + 2];
                        v.w = Dt[rr*72 + o*4 + 3] + p.bias[pp*64 + o*4 + 3];
                        *(float4*)(p.outf + (J0t + rr)*192 + pp*64 + o*4) = v;
                    }
                } else {
                    for (int idx = tid; idx < 1024; idx += 256) {
                        int rr = idx >> 3, o = idx & 7;
                        bf16 th[8], tl[8];
#pragma unroll
                        for (int u = 0; u < 8; u++) {
                            float v = fmaxf(Dt[rr*72 + o*8 + u] + p.bias[pp*64 + o*8 + u], 0.f);
                            bf16 hv = __float2bfloat16(v);
                            th[u] = hv;
                            tl[u] = __float2bfloat16(v - bf2f(hv));
                        }
                        size_t ob = (J0t + rr)*p.opitch + pp*64 + o*8;
                        *(uint4*)(p.oh + ob) = *(uint4*)th;
                        *(uint4*)(p.ol + ob) = *(uint4*)tl;
                    }
                }
                __syncthreads();
            }
        } else {
            float* sfin = Dt;                        // [64 c][132]
            uint32_t r[128];
            if (grp == 0) {
                TC_LD_X32(r,      ta);
                TC_LD_X32(r + 32, ta + 32);
                TC_LD_X32(r + 64, ta + 64);
                TC_LD_X32(r + 96, ta + 96);
            } else {
                TC_LD_X32(r,      ta + 128);
                TC_LD_X32(r + 32, ta + 160);
            }
            TC_WAIT_LD();
            if (grp == 1)
                for (int c = 0; c < 64; c++) sfin[c*132 + m] = __uint_as_float(r[c]);
            __syncthreads();
            if (grp == 0) {
                float s0 = 0.f, s1 = 0.f;
#pragma unroll
                for (int c = 0; c < 64; c++) {
                    float u = __uint_as_float(r[c]) + p.bias[c];
                    s0 += u * __uint_as_float(r[64 + c]);
                    s1 += u * sfin[c*132 + m];
                }
                float mx = fmaxf(s0, s1);
                float e0 = __expf(s0 - mx), e1 = __expf(s1 - mx);
                float inv = 1.f / (e0 + e1);
                float a0 = e0*inv, a1 = e1*inv;
                for (int c = 0; c < 64; c++)
                    sfin[c*132 + m] = a0*__uint_as_float(r[64 + c]) + a1*sfin[c*132 + m];
            }
            __syncthreads();
            int b = (int)(J0t / 20480);
            int joff = (int)(J0t % 20480);
            for (int idx = tid; idx < 2048; idx += 256) {
                int c = idx >> 5, o = idx & 31;
                float4 v;
                v.x = sfin[c*132 + o*4 + 0];
                v.y = sfin[c*132 + o*4 + 1];
                v.z = sfin[c*132 + o*4 + 2];
                v.w = sfin[c*132 + o*4 + 3];
                *(float4*)(p.outfin + (size_t)(b*64 + c)*20480 + joff + o*4) = v;
            }
            __syncthreads();
        }
    };

    for (int g = 0; g < GT; g++) {
        int buf = g & 1;
        if (g + 1 < GT) {
            if (g >= 1) MBAR_WAIT(sb + 8 + 8*(1 - buf), ((g - 1) >> 1) & 1);
            load_stage(g + 1, abase + (1 - buf)*STG_);
            cpa_commit();
            cpa_wait1();
        } else {
            cpa_wait0();
        }
        __syncthreads();
        if (wid == 0) {
            asm volatile("fence.proxy.async.shared::cta;" ::: "memory");
            if (elect1()) {
                int c = g % NCH, tile = g / NCH;
                uint32_t s0 = abase + buf*STG_;
                uint64_t ah = make_desc(s0);
                uint64_t al = make_desc(s0 + 16384);
                uint64_t wh = make_desc(s0 + 32768);
                uint64_t wl = make_desc(s0 + 32768 + WB);
                uint32_t d = tmem + (tile & 1)*256;
#pragma unroll
                for (int ks = 0; ks < 4; ks++) {
                    mma_bf(d, ah + 2*ks, wh + 2*ks, IDESC(NN), !(c == 0 && ks == 0));
                    mma_bf(d, ah + 2*ks, wl + 2*ks, IDESC(NN), true);
                    mma_bf(d, al + 2*ks, wh + 2*ks, IDESC(NN), true);
                }
                TC_COMMIT(sb + 8 + 8*buf);
            }
        }
        if (pending >= 0) { epilogue(pending); pending = -1; }
        if (g % NCH == NCH - 1) pending = g / NCH;
    }
    epilogue(pending);
    __syncthreads();
    if (tid == 0) { MBARRIER_INVAL(sb+8); MBARRIER_INVAL(sb+16); }
    if (wid == 0) { TC_RELINQ(); TC_DEALLOC(tmem, 512); }
#else
    for (int tile = 0; tile < JPB; tile++) {
        for (int mm = tid; mm < 128; mm += 256) {
            size_t J = J0 + (size_t)tile*128 + mm;
            if (MODE == 3) {
                float uu[64], h0[64], h1[64];
                for (int n = 0; n < 192; n++) {
                    float acc = 0.f;
                    for (int k = 0; k < K_; k++) {
                        float av = bf2f(p.ah[J*K_ + k]) + bf2f(p.al[J*K_ + k]);
                        size_t wi = ((size_t)(k >> 6)*NN + n)*64 + (k & 63);
                        acc += av * (bf2f(p.wh[wi]) + bf2f(p.wl[wi]));
                    }
                    if (n < 64) uu[n] = acc + p.bias[n];
                    else if (n < 128) h0[n-64] = acc;
                    else h1[n-128] = acc;
                }
                float s0 = 0.f, s1 = 0.f;
                for (int c = 0; c < 64; c++) { s0 += uu[c]*h0[c]; s1 += uu[c]*h1[c]; }
                float mx = fmaxf(s0, s1);
                float e0 = __expf(s0-mx), e1 = __expf(s1-mx), inv = 1.f/(e0+e1);
                int b = (int)(J/20480), rr = (int)(J%20480);
                for (int c = 0; c < 64; c++)
                    p.outfin[(size_t)(b*64+c)*20480 + rr] = (e0*h0[c]+e1*h1[c])*inv;
            } else {
                for (int n = 0; n < NN; n++) {
                    float acc = 0.f;
                    for (int k = 0; k < K_; k++) {
                        float av = bf2f(p.ah[J*K_ + k]) + bf2f(p.al[J*K_ + k]);
                        size_t wi = ((size_t)(k >> 6)*NN + n)*64 + (k & 63);
                        acc += av * (bf2f(p.wh[wi]) + bf2f(p.wl[wi]));
                    }
                    if (MODE == 0) p.outf[J*192 + n] = acc + p.bias[n];
                    else {
                        float v = fmaxf(acc + p.bias[n], 0.f);
                        bf16 hv = __float2bfloat16(v);
                        p.oh[J*p.opitch + n] = hv;
                        p.ol[J*p.opitch + n] = __float2bfloat16(v - bf2f(hv));
                    }
                }
            }
        }
    }
#endif
}

// ---------------- attention: block per (b,n), warp per head ----------------
__global__ __launch_bounds__(256) void k_attn() {
    __shared__ float sq[20*196];
    __shared__ float Ss[8][400];
    __shared__ bf16 soh[20*72], sol[20*72];
    int tid = threadIdx.x, wid = tid >> 5, lane = tid & 31;
    size_t Jb = (size_t)blockIdx.x * 20;

    for (int idx = tid; idx < 960; idx += 256) {
        int t = idx / 48, o = idx % 48;
        *(float4*)&sq[t*196 + o*4] = *(const float4*)(g_qkvJ + (Jb + t)*192 + o*4);
    }
    __syncthreads();
    int h = wid;
    float* S = Ss[h];
    const int hb = h*8;
    for (int idx = lane; idx < 400; idx += 32) {
        int t = idx / 20, s = idx % 20;
        if (s <= t) {
            float acc = 0.f;
#pragma unroll
            for (int d = 0; d < 8; d++) acc += sq[t*196 + hb + d] * sq[s*196 + 64 + hb + d];
            S[idx] = acc * 0.35355339059327373f;
        }
    }
    __syncwarp();
    if (lane < 20) {
        int t = lane;
        float mx = -1e30f;
        for (int s = 0; s <= t; s++) mx = fmaxf(mx, S[t*20 + s]);
        float sum = 0.f;
        for (int s = 0; s <= t; s++) { float e = __expf(S[t*20 + s] - mx); S[t*20 + s] = e; sum += e; }
        float inv = 1.f / sum;
        for (int s = 0; s <= t; s++) S[t*20 + s] *= inv;
    }
    __syncwarp();
    for (int idx = lane; idx < 160; idx += 32) {
        int d = idx / 20, t = idx % 20;
        float acc = 0.f;
        for (int s = 0; s <= t; s++) acc += S[t*20 + s] * sq[s*196 + 128 + hb + d];
        bf16 hv = __float2bfloat16(acc);
        soh[t*72 + hb + d] = hv;
        sol[t*72 + hb + d] = __float2bfloat16(acc - bf2f(hv));
    }
    __syncthreads();
    if (tid < 160) {
        int t = tid >> 3, o = tid & 7;
        size_t ob = (Jb + t)*64 + o*8;
        bf16 th[8], tl[8];
#pragma unroll
        for (int u = 0; u < 8; u++) { th[u] = soh[t*72 + o*8 + u]; tl[u] = sol[t*72 + o*8 + u]; }
        *(uint4*)(g_atth + ob) = *(uint4*)th;
        *(uint4*)(g_attl + ob) = *(uint4*)tl;
    }
}

// ---------------- transpose x2 -> xt[(b,t,c)][n] ----------------
__global__ __launch_bounds__(256) void k_xt() {
    __shared__ bf16 th[64][72], tl[64][72];
    int tid = threadIdx.x;
    int b = blockIdx.x, t = blockIdx.y, n0 = blockIdx.z * 64;
    for (int i = tid; i < 512; i += 256) {
        int r = i >> 3, c8 = i & 7;
        size_t src = ((size_t)(b*1024 + n0 + r)*20 + t)*320 + c8*8;
        *(uint4*)(&th[r][c8*8]) = *(const uint4*)(g_hch + src);
        *(uint4*)(&tl[r][c8*8]) = *(const uint4*)(g_hcl + src);
    }
    __syncthreads();
    for (int i = tid; i < 512; i += 256) {
        int c = i >> 3, n8 = i & 7;
        bf16 vh[8], vl[8];
#pragma unroll
        for (int u = 0; u < 8; u++) { vh[u] = th[n8*8 + u][c]; vl[u] = tl[n8*8 + u][c]; }
        size_t dst = (size_t)(b*1280 + t*64 + c)*1024 + n0 + n8*8;
        *(uint4*)(g_xth + dst) = *(uint4*)vh;
        *(uint4*)(g_xtl + dst) = *(uint4*)vl;
    }
}

// ---------------- nconv ----------------
#define NSTG 98304
#define NSMEM (1024 + 2*NSTG)
__device__ __forceinline__ void nc_load(int k0, uint32_t st,
                                        const bf16* Ah, const bf16* Al,
                                        int m0, int j0, int tid) {
    for (int g = tid; g < 6144; g += 256) {
        uint32_t dst; const void* src;
        if (g < 2048) {
            int part = g >> 10, e = g & 1023, r = e >> 3, c8 = e & 7;
            src = (part ? Al : Ah) + (size_t)(m0 + r)*1024 + k0 + c8*8;
            dst = st + part*16384 + SWZ(r*128 + c8*16);
        } else {
            int j = g - 2048;
            int part = j >> 11, e = j & 2047, r = e >> 3, c8 = e & 7;
            src = (part ? g_xtl : g_xth) + (size_t)(j0 + r)*1024 + k0 + c8*8;
            dst = st + 32768 + part*32768 + SWZ(r*128 + c8*16);
        }
        cpa16(dst, src);
    }
}

__global__ __launch_bounds__(256) void k_nconv_tc() {
    extern __shared__ char smem[];
    int tid = threadIdx.x, wid = tid >> 5, lane = tid & 31;
    int j0 = blockIdx.x * 256, m0 = blockIdx.y * 128, z = blockIdx.z;
    const bf16* Ah = g_Ah + (size_t)z*1024*1024;
    const bf16* Al = g_Al + (size_t)z*1024*1024;
    float* Dt = (float*)(smem + 1024);

#ifdef TC_PATH
    uint32_t sb = smem_u32(smem);
    if (wid == 0) TC_ALLOC(sb, 256);
    if (tid == 0) { MBARRIER_INIT(sb+8, 1); MBARRIER_INIT(sb+16, 1); }
    __syncthreads();
    uint32_t tmem;
    asm volatile("ld.shared.b32 %0, [%1];" : "=r"(tmem) : "r"(sb));
    uint32_t bufb = sb + 1024;

    nc_load(0, bufb, Ah, Al, m0, j0, tid);
    cpa_commit();
    int ph0 = 0, ph1 = 0;
    for (int ch = 0; ch < 16; ch++) {
        int buf = ch & 1;
        if (ch + 1 < 16) {
            int nb = 1 - buf;
            if (ch >= 1) {
                MBAR_WAIT(sb + 8 + 8*nb, (nb == 0) ? ph0 : ph1);
                if (nb == 0) ph0 ^= 1; else ph1 ^= 1;
            }
            nc_load((ch+1)*64, bufb + NSTG*nb, Ah, Al, m0, j0, tid);
            cpa_commit();
            cpa_wait1();
        } else {
            cpa_wait0();
        }
        __syncthreads();
        if (wid == 0) {
            asm volatile("fence.proxy.async.shared::cta;" ::: "memory");
            if (elect1()) {
                uint32_t s0 = bufb + NSTG*buf;
                uint64_t ah = make_desc(s0);
                uint64_t al = make_desc(s0 + 16384);
                uint64_t xh = make_desc(s0 + 32768);
                uint64_t xl = make_desc(s0 + 65536);
#pragma unroll
                for (int ks = 0; ks < 4; ks++) {
                    mma_bf(tmem, ah + 2*ks, xh + 2*ks, IDESC(256), !(ch == 0 && ks == 0));
                    mma_bf(tmem, ah + 2*ks, xl + 2*ks, IDESC(256), true);
                    mma_bf(tmem, al + 2*ks, xh + 2*ks, IDESC(256), true);
                }
                TC_COMMIT(sb + 8 + 8*buf);
            }
        }
    }
    MBAR_WAIT(sb + 16, ph1);
    TC_FENCE_AFTER();
    __syncthreads();
    {
        int sub = wid & 3, hf = wid >> 2;
        int m = sub*32 + lane;
#pragma unroll
        for (int i = 0; i < 4; i++) {
            uint32_t r[32];
            int cb = hf*128 + i*32;
            TC_LD_X32(r, tmem + cb);
            TC_WAIT_LD();
#pragma unroll
            for (int c = 0; c < 32; c++) Dt[(cb + c)*129 + m] = __uint_as_float(r[c]);
        }
    }
    __syncthreads();
    if (tid == 0) { MBARRIER_INVAL(sb+8); MBARRIER_INVAL(sb+16); }
    if (wid == 0) { TC_RELINQ(); TC_DEALLOC(tmem, 256); }
    __syncthreads();
#else
    for (int idx = tid; idx < 128*256; idx += 256) {
        int mm = idx >> 8, jl = idx & 255;
        float acc = 0.f;
        for (int kk = 0; kk < 1024; kk++) {
            float av = bf2f(Ah[(size_t)(m0+mm)*1024 + kk]) + bf2f(Al[(size_t)(m0+mm)*1024 + kk]);
            float xv = bf2f(g_xth[(size_t)(j0+jl)*1024 + kk]) + bf2f(g_xtl[(size_t)(j0+jl)*1024 + kk]);
            acc += av * xv;
        }
        Dt[jl*129 + mm] = acc;
    }
    __syncthreads();
#endif

    // coalesced epilogue: 512 runs of 128B, 8 lanes per run
    int b = j0 / 1280, t0 = (j0 % 1280) / 64;
    for (int idx = tid; idx < 4096; idx += 256) {
        int rn = idx >> 3, o = idx & 7;
        int w = rn >> 2, tq = rn & 3;
        size_t J = (size_t)(b*1024 + m0 + w)*20 + t0 + tq;
        size_t ob = J*320 + 64 + z*64 + o*8;
        bf16 th[8], tl[8];
#pragma unroll
        for (int u = 0; u < 8; u++) {
            float vv = Dt[(tq*64 + o*8 + u)*129 + w];
            bf16 hv = __float2bfloat16(vv);
            th[u] = hv;
            tl[u] = __float2bfloat16(vv - bf2f(hv));
        }
        *(uint4*)(g_hch + ob) = *(uint4*)th;
        *(uint4*)(g_hcl + ob) = *(uint4*)tl;
    }
}

// ---------------- launch ----------------
extern "C" void kernel_launch(void* const* d_in, const int* in_sizes, int n_in,
                              void* d_out, int out_size) {
    const float* x    = (const float*)d_in[0];
    const float* tem  = (const float*)d_in[1];
    float* out = (float*)d_out;

    GemmArgs base = {};
    float *p_qkvJ, *p_bqkv, *p_bo, *p_bh, *p_b3u;
    cudaGetSymbolAddress((void**)&p_qkvJ, g_qkvJ);
    cudaGetSymbolAddress((void**)&p_bqkv, g_bqkv);
    cudaGetSymbolAddress((void**)&p_bo,   g_bo);
    cudaGetSymbolAddress((void**)&p_bh,   g_bh);
    cudaGetSymbolAddress((void**)&p_b3u,  g_b3u);
    bf16 *p_xeh, *p_xel, *p_atth, *p_attl, *p_hch, *p_hcl, *p_h01h, *p_h01l;
    bf16 *p_wqkvh, *p_wqkvl, *p_woh, *p_wol, *p_wgh, *p_wgl, *p_w3h, *p_w3l;
    cudaGetSymbolAddress((void**)&p_xeh, g_xeh);   cudaGetSymbolAddress((void**)&p_xel, g_xel);
    cudaGetSymbolAddress((void**)&p_atth, g_atth); cudaGetSymbolAddress((void**)&p_attl, g_attl);
    cudaGetSymbolAddress((void**)&p_hch, g_hch);   cudaGetSymbolAddress((void**)&p_hcl, g_hcl);
    cudaGetSymbolAddress((void**)&p_h01h, g_h01h); cudaGetSymbolAddress((void**)&p_h01l, g_h01l);
    cudaGetSymbolAddress((void**)&p_wqkvh, g_wqkvh); cudaGetSymbolAddress((void**)&p_wqkvl, g_wqkvl);
    cudaGetSymbolAddress((void**)&p_woh, g_woh);   cudaGetSymbolAddress((void**)&p_wol, g_wol);
    cudaGetSymbolAddress((void**)&p_wgh, g_wgh);   cudaGetSymbolAddress((void**)&p_wgl, g_wgl);
    cudaGetSymbolAddress((void**)&p_w3h, g_w3h);   cudaGetSymbolAddress((void**)&p_w3l, g_w3l);

    const int S192 = 1024 + 2*(32768 + 2*192*128) + 36864;   // 201728
    const int S64  = 1024 + 2*(32768 + 2*64*128)  + 36864;   // 136192
    const int S128 = 1024 + 2*(32768 + 2*128*128) + 36864;   // 168960
    cudaFuncSetAttribute(k_gemm<128,192,0>, cudaFuncAttributeMaxDynamicSharedMemorySize, S192);
    cudaFuncSetAttribute(k_gemm<64,64,1>,   cudaFuncAttributeMaxDynamicSharedMemorySize, S64);
    cudaFuncSetAttribute(k_gemm<320,128,2>, cudaFuncAttributeMaxDynamicSharedMemorySize, S128);
    cudaFuncSetAttribute(k_gemm<128,192,3>, cudaFuncAttributeMaxDynamicSharedMemorySize, S192);
    cudaFuncSetAttribute(k_nconv_tc,        cudaFuncAttributeMaxDynamicSharedMemorySize, NSMEM);

    k_wsplit<<<370, 256>>>(
        (const float*)d_in[8],  (const float*)d_in[9],
        (const float*)d_in[10], (const float*)d_in[11],
        (const float*)d_in[12], (const float*)d_in[13],
        (const float*)d_in[14], (const float*)d_in[15],
        (const float*)d_in[16], (const float*)d_in[17],
        (const float*)d_in[18], (const float*)d_in[19],
        (const float*)d_in[20], (const float*)d_in[21],
        (const float*)d_in[22]);
    k_split_A<<<16384, 256>>>((const float*)d_in[2], (const float*)d_in[3],
                              (const float*)d_in[4], (const float*)d_in[5]);
    k_xe<<<4096, 256>>>(x, tem, (const float*)d_in[6], (const float*)d_in[7]);

    GemmArgs a = base;
    a.ah = p_xeh; a.al = p_xel; a.wh = p_wqkvh; a.wl = p_wqkvl;
    a.bias = p_bqkv; a.outf = p_qkvJ;
    k_gemm<128,192,0><<<GB_, 256, S192>>>(a);

    k_attn<<<16384, 256>>>();

    a = base;
    a.ah = p_atth; a.al = p_attl; a.wh = p_woh; a.wl = p_wol;
    a.bias = p_bo; a.oh = p_hch; a.ol = p_hcl; a.opitch = 320;
    k_gemm<64,64,1><<<GB_, 256, S64>>>(a);

    k_xt<<<dim3(16, 20, 16), 256>>>();
    k_nconv_tc<<<dim3(80, 8, 4), 256, NSMEM>>>();

    a = base;
    a.ah = p_hch; a.al = p_hcl; a.wh = p_wgh; a.wl = p_wgl;
    a.bias = p_bh; a.oh = p_h01h; a.ol = p_h01l; a.opitch = 128;
    k_gemm<320,128,2><<<GB_, 256, S128>>>(a);

    a = base;
    a.ah = p_h01h; a.al = p_h01l; a.wh = p_w3h; a.wl = p_w3l;
    a.bias = p_b3u; a.outfin = out;
    k_gemm<128,192,3><<<GB_, 256, S192>>>(a);
}

// round 9
// speedup vs baseline: 2.3533x; 1.3304x over previous
#include <cuda_runtime.h>
#include <cuda_bf16.h>
#include <cstdint>

#define B_   16
#define N_   1024
#define TO_  20
#define JT_  327680
#define JPB  8
#define GB_  320

#if defined(__CUDA_ARCH_FEAT_SM103_ALL) || defined(__CUDA_ARCH_FEAT_SM100_ALL)
#define TC_PATH 1
#endif

typedef __nv_bfloat16 bf16;

// chunk-blocked pre-swizzled layouts: [kc][row][64 bf16], unit o stored at o^(row&7)
__device__ float g_qkvJ[(size_t)JT_*192];
__device__ __align__(256) bf16 g_xeh[(size_t)JT_*128], g_xel[(size_t)JT_*128];
__device__ __align__(256) bf16 g_atth[(size_t)JT_*64], g_attl[(size_t)JT_*64];
__device__ __align__(256) bf16 g_hch[(size_t)JT_*320], g_hcl[(size_t)JT_*320];
__device__ __align__(256) bf16 g_xth[(size_t)20480*1024], g_xtl[(size_t)20480*1024];
__device__ __align__(256) bf16 g_h01h[(size_t)JT_*128], g_h01l[(size_t)JT_*128];
__device__ __align__(256) bf16 g_Ah[4*1024*1024], g_Al[4*1024*1024];
__device__ __align__(256) bf16 g_wqkvh[24576], g_wqkvl[24576];
__device__ __align__(256) bf16 g_woh[4096],   g_wol[4096];
__device__ __align__(256) bf16 g_wgh[40960],  g_wgl[40960];
__device__ __align__(256) bf16 g_w3h[24576],  g_w3l[24576];
__device__ float g_bqkv[192], g_bo[64], g_bh[128], g_b3u[64];

__device__ __forceinline__ float bf2f(bf16 v) { return __bfloat162float(v); }
__device__ __forceinline__ uint32_t smem_u32(const void* p) {
    uint32_t a;
    asm("{ .reg .u64 t; cvta.to.shared.u64 t, %1; cvt.u32.u64 %0, t; }" : "=r"(a) : "l"(p));
    return a;
}
__device__ __forceinline__ int swe(int row, int k) { return ((((k >> 3) ^ (row & 7)) << 3) | (k & 7)); }

#ifdef TC_PATH
__device__ __forceinline__ uint32_t elect1() {
    uint32_t p;
    asm volatile("{\n\t.reg .pred p;\n\telect.sync _|p, 0xFFFFFFFF;\n\tselp.b32 %0, 1, 0, p;\n\t}" : "=r"(p));
    return p;
}
#define MBARRIER_INIT(addr, cnt) \
    asm volatile("mbarrier.init.shared.b64 [%0], %1;" :: "r"(addr), "r"(cnt) : "memory")
#define MBARRIER_INVAL(addr) \
    asm volatile("mbarrier.inval.shared.b64 [%0];" :: "r"(addr) : "memory")
#define MBAR_EXPECT(mbar, bytes) \
    asm volatile("mbarrier.arrive.expect_tx.shared.b64 _, [%0], %1;" \
        :: "r"((uint32_t)(mbar)), "r"((uint32_t)(bytes)) : "memory")
#define BULK_G2S(dst, src, bytes, mbar) \
    asm volatile("cp.async.bulk.shared::cluster.global.mbarrier::complete_tx::bytes [%0], [%1], %2, [%3];" \
        :: "r"((uint32_t)(dst)), "l"(src), "r"((uint32_t)(bytes)), "r"((uint32_t)(mbar)) : "memory")
#define MBAR_WAIT(mb, par) do { \
    uint32_t _m = (uint32_t)(mb), _p = (uint32_t)(par), _d; \
    asm volatile("{\n\t.reg .pred p;\n\t" \
        "mbarrier.try_wait.parity.acquire.cta.shared::cta.b64 p, [%1], %2;\n\t" \
        "selp.b32 %0, 1, 0, p;\n\t}" : "=r"(_d) : "r"(_m), "r"(_p) : "memory"); \
    if (!_d) { \
        asm volatile("{\n\t.reg .pred P1;\n\t" \
            "WL_%=:\n\t" \
            "mbarrier.try_wait.parity.acquire.cta.shared::cta.b64 P1, [%0], %1, 0x989680;\n\t" \
            "@P1 bra.uni WD_%=;\n\tbra.uni WL_%=;\n\tWD_%=:\n\t}" \
            :: "r"(_m), "r"(_p) : "memory"); \
    } \
} while(0)
#define TC_ALLOC(saddr, n) \
    asm volatile("tcgen05.alloc.cta_group::1.sync.aligned.shared::cta.b32 [%0], %1;" \
        :: "r"((uint32_t)(saddr)), "r"((uint32_t)(n)) : "memory")
#define TC_DEALLOC(tmem, n) \
    asm volatile("tcgen05.dealloc.cta_group::1.sync.aligned.b32 %0, %1;" :: "r"(tmem), "r"((uint32_t)(n)))
#define TC_RELINQ() asm volatile("tcgen05.relinquish_alloc_permit.cta_group::1.sync.aligned;")
#define TC_COMMIT(mbar) \
    asm volatile("tcgen05.commit.cta_group::1.mbarrier::arrive::one.shared::cluster.b64 [%0];" \
        :: "r"((uint32_t)(mbar)) : "memory")
#define TC_FENCE_AFTER() asm volatile("tcgen05.fence::after_thread_sync;" ::: "memory")
#define TC_WAIT_LD() asm volatile("tcgen05.wait::ld.sync.aligned;" ::: "memory")
#define TC_LD_X32(r, ta) \
    asm volatile("tcgen05.ld.sync.aligned.32x32b.x32.b32 " \
        "{%0, %1, %2, %3, %4, %5, %6, %7, %8, %9, %10, %11, %12, %13, %14, %15, " \
        " %16, %17, %18, %19, %20, %21, %22, %23, %24, %25, %26, %27, %28, %29, %30, %31}, [%32];" \
        : "=r"((r)[0]),  "=r"((r)[1]),  "=r"((r)[2]),  "=r"((r)[3]), \
          "=r"((r)[4]),  "=r"((r)[5]),  "=r"((r)[6]),  "=r"((r)[7]), \
          "=r"((r)[8]),  "=r"((r)[9]),  "=r"((r)[10]), "=r"((r)[11]), \
          "=r"((r)[12]), "=r"((r)[13]), "=r"((r)[14]), "=r"((r)[15]), \
          "=r"((r)[16]), "=r"((r)[17]), "=r"((r)[18]), "=r"((r)[19]), \
          "=r"((r)[20]), "=r"((r)[21]), "=r"((r)[22]), "=r"((r)[23]), \
          "=r"((r)[24]), "=r"((r)[25]), "=r"((r)[26]), "=r"((r)[27]), \
          "=r"((r)[28]), "=r"((r)[29]), "=r"((r)[30]), "=r"((r)[31]) \
        : "r"(ta))
__device__ __forceinline__ uint64_t make_desc(uint32_t addr) {
    return 0x4000404000010000ULL | (uint64_t)((addr >> 4) & 0x3FFF);
}
__device__ __forceinline__ void mma_bf(uint32_t d, uint64_t a, uint64_t b, uint32_t idesc, bool acc) {
    uint32_t en = acc ? 1u : 0u;
    asm volatile("{\n\t.reg .pred p;\n\tsetp.ne.u32 p, %5, 0;\n\t"
        "tcgen05.mma.cta_group::1.kind::f16 [%0], %1, %2, %3, {%4, %4, %4, %4}, p;\n\t}"
        :: "r"(d), "l"(a), "l"(b), "r"(idesc), "r"(0u), "r"(en) : "memory");
}
#define IDESC(n) (0x8000490u | (((n)/8) << 17))
#endif

// ---------------- weight split/pack (pre-swizzled) ----------------
__global__ void k_wsplit(const float* __restrict__ wq, const float* __restrict__ bq,
                         const float* __restrict__ wk, const float* __restrict__ bk,
                         const float* __restrict__ wv, const float* __restrict__ bv,
                         const float* __restrict__ wo, const float* __restrict__ bo,
                         const float* __restrict__ wg0, const float* __restrict__ bg0,
                         const float* __restrict__ wg1, const float* __restrict__ bg1,
                         const float* __restrict__ wadp, const float* __restrict__ badp,
                         const float* __restrict__ w0f) {
    int i = blockIdx.x * 256 + threadIdx.x;
    if (i < 24576) {
        int c = i / 12288, rem = i % 12288, r = rem / 64, k = rem & 63, col = c*64 + k;
        int s = r / 64, rr = r % 64;
        const float* W = (s == 0) ? wq : (s == 1) ? wk : wv;
        float v = (col < 96) ? W[rr*96 + col] : 0.f;
        bf16 h = __float2bfloat16(v);
        int si = (c*192 + r)*64 + swe(r, k);
        g_wqkvh[si] = h; g_wqkvl[si] = __float2bfloat16(v - bf2f(h));
    } else if (i < 28672) {
        int j = i - 24576;
        int n = j >> 6, k = j & 63;
        float v = wo[j];
        bf16 h = __float2bfloat16(v);
        int si = (n << 6) + swe(n, k);
        g_woh[si] = h; g_wol[si] = __float2bfloat16(v - bf2f(h));
    } else if (i < 69632) {
        int j = i - 28672;
        int c = j / 8192, rem = j % 8192, r = rem / 64, k = rem & 63, col = c*64 + k;
        float v;
        if (r < 64) v = (col < 192) ? wg0[r*192 + col] : 0.f;
        else {
            int rr = r - 64;
            if (col < 64) v = wg1[rr*192 + col];
            else if (col >= 192) v = wg1[rr*192 + col - 128];
            else v = 0.f;
        }
        bf16 h = __float2bfloat16(v);
        int si = (c*128 + r)*64 + swe(r, k);
        g_wgh[si] = h; g_wgl[si] = __float2bfloat16(v - bf2f(h));
    } else if (i < 94208) {
        int j = i - 69632;
        int c = j / 12288, rem = j % 12288, r = rem / 64, k = rem & 63, col = c*64 + k;
        float v;
        if (r < 64)       v = wadp[r*128 + col];
        else if (r < 128) v = (col < 64) ? w0f[(r-64)*64 + col] : 0.f;
        else              v = (col >= 64) ? w0f[(r-128)*64 + col - 64] : 0.f;
        bf16 h = __float2bfloat16(v);
        int si = (c*192 + r)*64 + swe(r, k);
        g_w3h[si] = h; g_w3l[si] = __float2bfloat16(v - bf2f(h));
    } else if (i < 94656) {
        int j = i - 94208;
        if (j < 192)      g_bqkv[j] = (j < 64) ? bq[j] : (j < 128) ? bk[j-64] : bv[j-128];
        else if (j < 256) g_bo[j-192] = bo[j-192];
        else if (j < 384) { int j2 = j-256; g_bh[j2] = (j2 < 64) ? bg0[j2] : bg1[j2-64]; }
        else              g_b3u[j-384] = badp[j-384];
    }
}

// ---------------- split graph matrices into [z][16][1024][64] pre-swizzled ----------------
__global__ void k_split_A(const float* __restrict__ A0, const float* __restrict__ A1,
                          const float* __restrict__ A2, const float* __restrict__ A3) {
    int u = blockIdx.x * 256 + threadIdx.x;
    int z = u >> 17, rem = u & 131071;
    int m = rem >> 7, uo = rem & 127;
    int kc = uo >> 3, o = uo & 7;
    const float* A = (z == 0) ? A0 : (z == 1) ? A1 : (z == 2) ? A2 : A3;
    const float* src = A + (size_t)m*1024 + uo*8;
    bf16 th[8], tl[8];
#pragma unroll
    for (int e = 0; e < 8; e++) {
        float v = src[e];
        bf16 h = __float2bfloat16(v);
        th[e] = h; tl[e] = __float2bfloat16(v - bf2f(h));
    }
    size_t dst = (((size_t)(z*16 + kc)*1024 + m) << 6) + ((o ^ (m & 7)) << 3);
    *(uint4*)(g_Ah + dst) = *(uint4*)th;
    *(uint4*)(g_Al + dst) = *(uint4*)tl;
}

// ---------------- fused dilated conv + tem slice -> xe [2][JT][64] ----------------
__global__ __launch_bounds__(256) void k_xe(const float* __restrict__ x,
                                            const float* __restrict__ tem,
                                            const float* __restrict__ w,
                                            const float* __restrict__ bias) {
    __shared__ float pool[9376];
    float* xs = pool;
    float* ws = pool + 3072;
    float* bs = pool + 9312;
    int tid = threadIdx.x;
    int b = blockIdx.x >> 8, n0 = (blockIdx.x & 255) * 4;
    for (int i = tid; i < 64*96; i += 256) { int o = i / 96, kk = i % 96; ws[kk*65 + o] = w[i]; }
    if (tid < 64) bs[tid] = bias[tid];
    for (int i = tid; i < 3072; i += 256) {
        int nn = i / 768, r = i % 768, ci = r / 24, tt = r % 24;
        xs[(nn*32 + ci)*24 + tt] = x[((size_t)(b*32 + ci)*1024 + n0 + nn)*24 + tt];
    }
    __syncthreads();
    int co = tid & 63, nn = tid >> 6;
    float acc[20];
#pragma unroll
    for (int t = 0; t < 20; t++) acc[t] = bs[co];
    for (int ci = 0; ci < 32; ci++) {
        float w0 = ws[(ci*3+0)*65 + co], w1 = ws[(ci*3+1)*65 + co], w2 = ws[(ci*3+2)*65 + co];
        const float* xr = &xs[(nn*32 + ci)*24];
#pragma unroll
        for (int t = 0; t < 20; t++) acc[t] += w0*xr[t] + w1*xr[t+2] + w2*xr[t+4];
    }
    __syncthreads();
    float* sxe = pool;
#pragma unroll
    for (int t = 0; t < 20; t++) sxe[(nn*20 + t)*96 + co] = fmaxf(acc[t], 0.f);
    for (int i = tid; i < 2560; i += 256) {
        int nn2 = i / 640, r = i % 640, ci = r / 20, t = r % 20;
        sxe[(nn2*20 + t)*96 + 64 + ci] = tem[((size_t)(b*32 + ci)*1024 + n0 + nn2)*24 + 4 + t];
    }
    __syncthreads();
    for (int idx = tid; idx < 2560; idx += 256) {
        int half = idx >= 1280;
        int e = half ? idx - 1280 : idx;
        int rr = e >> 4, uo = e & 15;
        int kc = uo >> 3, o = uo & 7;
        int nn2 = rr / 20, t = rr % 20;
        size_t J = (size_t)((b*1024 + n0 + nn2)*20 + t);
        const float* srow = &sxe[rr*96];
        bf16 tmp[8];
#pragma unroll
        for (int u = 0; u < 8; u++) {
            int c = uo*8 + u;
            float vv = (c < 96) ? srow[c] : 0.f;
            bf16 hv = __float2bfloat16(vv);
            tmp[u] = half ? __float2bfloat16(vv - bf2f(hv)) : hv;
        }
        size_t dst = (((size_t)kc*JT_ + J) << 6) + ((o ^ (J & 7)) << 3);
        *(uint4*)((half ? g_xel : g_xeh) + dst) = *(uint4*)tmp;
    }
}

// ---------------- persistent multi-tile tensor-core GEMM (bulk-copy pipeline) ----------------
struct GemmArgs {
    const bf16 *ah, *al;      // [K/64][JT][64] pre-swizzled
    const bf16 *wh, *wl;      // [K/64][N][64] pre-swizzled
    const float* bias;
    float* outf;              // MODE 0
    bf16 *oh, *ol;            // MODE 1/2: [Nout/64][JT][64]
    float* outfin;            // MODE 3
};

template<int K_, int NN, int MODE>
__global__ __launch_bounds__(256) void k_gemm(GemmArgs p) {
    constexpr int NCH = K_ / 64;
    constexpr int WB  = NN * 128;
    constexpr int STG_ = 32768 + 2*WB;
    constexpr int GT  = JPB * NCH;
    extern __shared__ char smem[];
    int tid = threadIdx.x, wid = tid >> 5, lane = tid & 31;
    size_t J0 = (size_t)blockIdx.x * (JPB*128);
    float* Dt = (float*)(smem + 1024 + 2*STG_);

#ifdef TC_PATH
    uint32_t sb = smem_u32(smem);
    if (wid == 0) TC_ALLOC(sb, 512);
    if (tid == 0) {
        MBARRIER_INIT(sb+8, 1);  MBARRIER_INIT(sb+16, 1);   // full[0], full[1]
        MBARRIER_INIT(sb+24, 1); MBARRIER_INIT(sb+32, 1);   // mma[0],  mma[1]
    }
    __syncthreads();
    uint32_t tmem;
    asm volatile("ld.shared.b32 %0, [%1];" : "=r"(tmem) : "r"(sb));
    uint32_t abase = sb + 1024;

    auto load_stage = [&](int g, uint32_t st) {
        int tile = g / NCH, c = g % NCH;
        uint32_t mb = sb + 8 + 8*(g & 1);
        MBAR_EXPECT(mb, 32768 + 2*WB);
        const bf16* as = p.ah + (((size_t)c*JT_ + J0 + tile*128) << 6);
        const bf16* ls = p.al + (((size_t)c*JT_ + J0 + tile*128) << 6);
        BULK_G2S(st,          as, 16384, mb);
        BULK_G2S(st + 16384,  ls, 16384, mb);
        BULK_G2S(st + 32768,      p.wh + ((size_t)c*NN << 6), WB, mb);
        BULK_G2S(st + 32768 + WB, p.wl + ((size_t)c*NN << 6), WB, mb);
    };

    int pending = -1;
    int sub = wid & 3, grp = wid >> 2;
    int m = sub*32 + lane;

    // epilogue: caller has already ensured the tile's last-stage commit is visible
    auto epilogue = [&](int tile) {
        TC_FENCE_AFTER();
        size_t J0t = J0 + (size_t)tile*128;
        uint32_t ta = tmem + (tile & 1)*256;
        if (MODE != 3) {
#pragma unroll
            for (int pp = 0; pp < NN/64; pp++) {
                uint32_t r[32];
                TC_LD_X32(r, ta + pp*64 + grp*32);
                TC_WAIT_LD();
#pragma unroll
                for (int c = 0; c < 32; c++) Dt[m*72 + grp*32 + c] = __uint_as_float(r[c]);
                __syncthreads();
                if (MODE == 0) {
                    for (int idx = tid; idx < 2048; idx += 256) {
                        int rr = idx >> 4, o = idx & 15;
                        float4 v;
                        v.x = Dt[rr*72 + o*4 + 0] + p.bias[pp*64 + o*4 + 0];
                        v.y = Dt[rr*72 + o*4 + 1] + p.bias[pp*64 + o*4 + 1];
                        v.z = Dt[rr*72 + o*4 + 2] + p.bias[pp*64 + o*4 + 2];
                        v.w = Dt[rr*72 + o*4 + 3] + p.bias[pp*64 + o*4 + 3];
                        *(float4*)(p.outf + (J0t + rr)*192 + pp*64 + o*4) = v;
                    }
                } else {
                    for (int idx = tid; idx < 1024; idx += 256) {
                        int rr = idx >> 3, o = idx & 7;
                        size_t J = J0t + rr;
                        bf16 th[8], tl[8];
#pragma unroll
                        for (int u = 0; u < 8; u++) {
                            float v = fmaxf(Dt[rr*72 + o*8 + u] + p.bias[pp*64 + o*8 + u], 0.f);
                            bf16 hv = __float2bfloat16(v);
                            th[u] = hv;
                            tl[u] = __float2bfloat16(v - bf2f(hv));
                        }
                        size_t ob = (((size_t)pp*JT_ + J) << 6) + ((o ^ (J & 7)) << 3);
                        *(uint4*)(p.oh + ob) = *(uint4*)th;
                        *(uint4*)(p.ol + ob) = *(uint4*)tl;
                    }
                }
                __syncthreads();
            }
        } else {
            float* sfin = Dt;
            uint32_t r[128];
            if (grp == 0) {
                TC_LD_X32(r,      ta);
                TC_LD_X32(r + 32, ta + 32);
                TC_LD_X32(r + 64, ta + 64);
                TC_LD_X32(r + 96, ta + 96);
            } else {
                TC_LD_X32(r,      ta + 128);
                TC_LD_X32(r + 32, ta + 160);
            }
            TC_WAIT_LD();
            if (grp == 1)
                for (int c = 0; c < 64; c++) sfin[c*132 + m] = __uint_as_float(r[c]);
            __syncthreads();
            if (grp == 0) {
                float s0 = 0.f, s1 = 0.f;
#pragma unroll
                for (int c = 0; c < 64; c++) {
                    float u = __uint_as_float(r[c]) + p.bias[c];
                    s0 += u * __uint_as_float(r[64 + c]);
                    s1 += u * sfin[c*132 + m];
                }
                float mx = fmaxf(s0, s1);
                float e0 = __expf(s0 - mx), e1 = __expf(s1 - mx);
                float inv = 1.f / (e0 + e1);
                float a0 = e0*inv, a1 = e1*inv;
                for (int c = 0; c < 64; c++)
                    sfin[c*132 + m] = a0*__uint_as_float(r[64 + c]) + a1*sfin[c*132 + m];
            }
            __syncthreads();
            int b = (int)(J0t / 20480);
            int joff = (int)(J0t % 20480);
            for (int idx = tid; idx < 2048; idx += 256) {
                int c = idx >> 5, o = idx & 31;
                float4 v;
                v.x = sfin[c*132 + o*4 + 0];
                v.y = sfin[c*132 + o*4 + 1];
                v.z = sfin[c*132 + o*4 + 2];
                v.w = sfin[c*132 + o*4 + 3];
                *(float4*)(p.outfin + (size_t)(b*64 + c)*20480 + joff + o*4) = v;
            }
            __syncthreads();
        }
    };

    if (wid == 0) { if (elect1()) { load_stage(0, abase); } }
    for (int g = 0; g < GT; g++) {
        int buf = g & 1;
        // ALL threads track mma phases sequentially (buffer-reuse + epilogue guard)
        if (g >= 1) MBAR_WAIT(sb + 24 + 8*((g - 1) & 1), ((g - 1) >> 1) & 1);
        if (wid == 0) {
            if (elect1()) {
                if (g + 1 < GT) load_stage(g + 1, abase + (1 - buf)*STG_);
                MBAR_WAIT(sb + 8 + 8*buf, (g >> 1) & 1);
                int c = g % NCH, tile = g / NCH;
                uint32_t s0 = abase + buf*STG_;
                uint64_t ah = make_desc(s0);
                uint64_t al = make_desc(s0 + 16384);
                uint64_t wh = make_desc(s0 + 32768);
                uint64_t wl = make_desc(s0 + 32768 + WB);
                uint32_t d = tmem + (tile & 1)*256;
#pragma unroll
                for (int ks = 0; ks < 4; ks++) {
                    mma_bf(d, ah + 2*ks, wh + 2*ks, IDESC(NN), !(c == 0 && ks == 0));
                    mma_bf(d, ah + 2*ks, wl + 2*ks, IDESC(NN), true);
                    mma_bf(d, al + 2*ks, wh + 2*ks, IDESC(NN), true);
                }
                TC_COMMIT(sb + 24 + 8*buf);
            }
        }
        if (pending >= 0) { epilogue(pending); pending = -1; }
        if (g % NCH == NCH - 1) pending = g / NCH;
    }
    // final tile: wait last stage commit (all threads, sequentially tracked)
    MBAR_WAIT(sb + 24 + 8*((GT - 1) & 1), ((GT - 1) >> 1) & 1);
    epilogue(pending);
    __syncthreads();
    if (tid == 0) { MBARRIER_INVAL(sb+8); MBARRIER_INVAL(sb+16); MBARRIER_INVAL(sb+24); MBARRIER_INVAL(sb+32); }
    if (wid == 0) { TC_RELINQ(); TC_DEALLOC(tmem, 512); }
#else
    for (int tile = 0; tile < JPB; tile++) {
        for (int mm = tid; mm < 128; mm += 256) {
            size_t J = J0 + (size_t)tile*128 + mm;
            float res[MODE == 3 ? 192 : NN];
            for (int n = 0; n < (MODE == 3 ? 192 : NN); n++) {
                float acc = 0.f;
                for (int k = 0; k < K_; k++) {
                    size_t ai = (((size_t)(k >> 6)*JT_ + J) << 6) + swe((int)(J & 7), k & 63);
                    float av = bf2f(p.ah[ai]) + bf2f(p.al[ai]);
                    size_t wi = (((size_t)(k >> 6)*NN + n) << 6) + swe(n, k & 63);
                    acc += av * (bf2f(p.wh[wi]) + bf2f(p.wl[wi]));
                }
                res[n] = acc;
            }
            if (MODE == 0) {
                for (int n = 0; n < NN; n++) p.outf[J*192 + n] = res[n] + p.bias[n];
            } else if (MODE == 3) {
                float s0 = 0.f, s1 = 0.f;
                for (int c = 0; c < 64; c++) {
                    float u = res[c] + p.bias[c];
                    s0 += u*res[64+c]; s1 += u*res[128+c];
                }
                float mx = fmaxf(s0, s1);
                float e0 = __expf(s0-mx), e1 = __expf(s1-mx), inv = 1.f/(e0+e1);
                int b = (int)(J/20480), rr = (int)(J%20480);
                for (int c = 0; c < 64; c++)
                    p.outfin[(size_t)(b*64+c)*20480 + rr] = (e0*res[64+c]+e1*res[128+c])*inv;
            } else {
                for (int n = 0; n < NN; n++) {
                    float v = fmaxf(res[n] + p.bias[n], 0.f);
                    bf16 hv = __float2bfloat16(v);
                    size_t ob = (((size_t)(n >> 6)*JT_ + J) << 6) + swe((int)(J & 7), n & 63);
                    p.oh[ob] = hv;
                    p.ol[ob] = __float2bfloat16(v - bf2f(hv));
                }
            }
        }
    }
#endif
}

// ---------------- attention: block per (b,n), warp per head ----------------
__global__ __launch_bounds__(256) void k_attn() {
    __shared__ float sq[20*196];
    __shared__ float Ss[8][400];
    __shared__ bf16 soh[20*72], sol[20*72];
    int tid = threadIdx.x, wid = tid >> 5, lane = tid & 31;
    size_t Jb = (size_t)blockIdx.x * 20;

    for (int idx = tid; idx < 960; idx += 256) {
        int t = idx / 48, o = idx % 48;
        *(float4*)&sq[t*196 + o*4] = *(const float4*)(g_qkvJ + (Jb + t)*192 + o*4);
    }
    __syncthreads();
    int h = wid;
    float* S = Ss[h];
    const int hb = h*8;
    for (int idx = lane; idx < 400; idx += 32) {
        int t = idx / 20, s = idx % 20;
        if (s <= t) {
            float acc = 0.f;
#pragma unroll
            for (int d = 0; d < 8; d++) acc += sq[t*196 + hb + d] * sq[s*196 + 64 + hb + d];
            S[idx] = acc * 0.35355339059327373f;
        }
    }
    __syncwarp();
    if (lane < 20) {
        int t = lane;
        float mx = -1e30f;
        for (int s = 0; s <= t; s++) mx = fmaxf(mx, S[t*20 + s]);
        float sum = 0.f;
        for (int s = 0; s <= t; s++) { float e = __expf(S[t*20 + s] - mx); S[t*20 + s] = e; sum += e; }
        float inv = 1.f / sum;
        for (int s = 0; s <= t; s++) S[t*20 + s] *= inv;
    }
    __syncwarp();
    for (int idx = lane; idx < 160; idx += 32) {
        int d = idx / 20, t = idx % 20;
        float acc = 0.f;
        for (int s = 0; s <= t; s++) acc += S[t*20 + s] * sq[s*196 + 128 + hb + d];
        bf16 hv = __float2bfloat16(acc);
        soh[t*72 + hb + d] = hv;
        sol[t*72 + hb + d] = __float2bfloat16(acc - bf2f(hv));
    }
    __syncthreads();
    if (tid < 160) {
        int t = tid >> 3, o = tid & 7;
        size_t J = Jb + t;
        size_t ob = (J << 6) + ((o ^ (J & 7)) << 3);
        bf16 th[8], tl[8];
#pragma unroll
        for (int u = 0; u < 8; u++) { th[u] = soh[t*72 + o*8 + u]; tl[u] = sol[t*72 + o*8 + u]; }
        *(uint4*)(g_atth + ob) = *(uint4*)th;
        *(uint4*)(g_attl + ob) = *(uint4*)tl;
    }
}

// ---------------- transpose x2 (hc kc=0) -> xt[kc][(b,t,c)][64] pre-swizzled ----------------
__global__ __launch_bounds__(256) void k_xt() {
    __shared__ bf16 th[64][72], tl[64][72];
    int tid = threadIdx.x;
    int b = blockIdx.x, t = blockIdx.y, n0 = blockIdx.z * 64;
    for (int i = tid; i < 512; i += 256) {
        int r = i >> 3, o = i & 7;
        size_t J = ((size_t)(b*1024 + n0 + r)*20 + t);
        size_t src = (J << 6) + ((o ^ (J & 7)) << 3);
        *(uint4*)(&th[r][o*8]) = *(const uint4*)(g_hch + src);
        *(uint4*)(&tl[r][o*8]) = *(const uint4*)(g_hcl + src);
    }
    __syncthreads();
    for (int i = tid; i < 512; i += 256) {
        int c = i >> 3, n8 = i & 7;
        bf16 vh[8], vl[8];
#pragma unroll
        for (int u = 0; u < 8; u++) { vh[u] = th[n8*8 + u][c]; vl[u] = tl[n8*8 + u][c]; }
        int j = b*1280 + t*64 + c;
        size_t dst = (((size_t)blockIdx.z*20480 + j) << 6) + ((n8 ^ (j & 7)) << 3);
        *(uint4*)(g_xth + dst) = *(uint4*)vh;
        *(uint4*)(g_xtl + dst) = *(uint4*)vl;
    }
}

// ---------------- nconv (bulk-copy pipeline) ----------------
#define NSTG 98304
#define NSMEM (1024 + 2*NSTG)
__global__ __launch_bounds__(256) void k_nconv_tc() {
    extern __shared__ char smem[];
    int tid = threadIdx.x, wid = tid >> 5, lane = tid & 31;
    int j0 = blockIdx.x * 256, m0 = blockIdx.y * 128, z = blockIdx.z;
    float* Dt = (float*)(smem + 1024);

#ifdef TC_PATH
    uint32_t sb = smem_u32(smem);
    if (wid == 0) TC_ALLOC(sb, 256);
    if (tid == 0) {
        MBARRIER_INIT(sb+8, 1);  MBARRIER_INIT(sb+16, 1);
        MBARRIER_INIT(sb+24, 1); MBARRIER_INIT(sb+32, 1);
    }
    __syncthreads();
    uint32_t tmem;
    asm volatile("ld.shared.b32 %0, [%1];" : "=r"(tmem) : "r"(sb));
    uint32_t bufb = sb + 1024;

    auto load_stage = [&](int kc, uint32_t st) {
        uint32_t mb = sb + 8 + 8*(kc & 1);
        MBAR_EXPECT(mb, NSTG);
        BULK_G2S(st,         g_Ah + (((size_t)(z*16 + kc)*1024 + m0) << 6), 16384, mb);
        BULK_G2S(st + 16384, g_Al + (((size_t)(z*16 + kc)*1024 + m0) << 6), 16384, mb);
        BULK_G2S(st + 32768, g_xth + (((size_t)kc*20480 + j0) << 6), 32768, mb);
        BULK_G2S(st + 65536, g_xtl + (((size_t)kc*20480 + j0) << 6), 32768, mb);
    };

    if (wid == 0) { if (elect1()) { load_stage(0, bufb); } }
    for (int ch = 0; ch < 16; ch++) {
        int buf = ch & 1;
        if (ch >= 1) MBAR_WAIT(sb + 24 + 8*((ch - 1) & 1), ((ch - 1) >> 1) & 1);
        if (wid == 0) {
            if (elect1()) {
                if (ch + 1 < 16) load_stage(ch + 1, bufb + (1 - buf)*NSTG);
                MBAR_WAIT(sb + 8 + 8*buf, (ch >> 1) & 1);
                uint32_t s0 = bufb + buf*NSTG;
                uint64_t ah = make_desc(s0);
                uint64_t al = make_desc(s0 + 16384);
                uint64_t xh = make_desc(s0 + 32768);
                uint64_t xl = make_desc(s0 + 65536);
#pragma unroll
                for (int ks = 0; ks < 4; ks++) {
                    mma_bf(tmem, ah + 2*ks, xh + 2*ks, IDESC(256), !(ch == 0 && ks == 0));
                    mma_bf(tmem, ah + 2*ks, xl + 2*ks, IDESC(256), true);
                    mma_bf(tmem, al + 2*ks, xh + 2*ks, IDESC(256), true);
                }
                TC_COMMIT(sb + 24 + 8*buf);
            }
        }
    }
    MBAR_WAIT(sb + 24 + 8, 1);    // stage 15 commit (all threads phase-tracked)
    TC_FENCE_AFTER();
    __syncthreads();
    {
        int sub = wid & 3, hf = wid >> 2;
        int m = sub*32 + lane;
#pragma unroll
        for (int i = 0; i < 4; i++) {
            uint32_t r[32];
            int cb = hf*128 + i*32;
            TC_LD_X32(r, tmem + cb);
            TC_WAIT_LD();
#pragma unroll
            for (int c = 0; c < 32; c++) Dt[(cb + c)*129 + m] = __uint_as_float(r[c]);
        }
    }
    __syncthreads();
    if (tid == 0) { MBARRIER_INVAL(sb+8); MBARRIER_INVAL(sb+16); MBARRIER_INVAL(sb+24); MBARRIER_INVAL(sb+32); }
    if (wid == 0) { TC_RELINQ(); TC_DEALLOC(tmem, 256); }
    __syncthreads();
#else
    for (int idx = tid; idx < 128*256; idx += 256) {
        int mm = idx >> 8, jl = idx & 255;
        int gm = m0 + mm, gj = j0 + jl;
        float acc = 0.f;
        for (int k = 0; k < 1024; k++) {
            size_t ai = (((size_t)(z*16 + (k >> 6))*1024 + gm) << 6) + swe(gm & 7, k & 63);
            size_t xi = (((size_t)(k >> 6)*20480 + gj) << 6) + swe(gj & 7, k & 63);
            acc += (bf2f(g_Ah[ai]) + bf2f(g_Al[ai])) * (bf2f(g_xth[xi]) + bf2f(g_xtl[xi]));
        }
        Dt[jl*129 + mm] = acc;
    }
    __syncthreads();
#endif

    int b = j0 / 1280, t0 = (j0 % 1280) / 64;
    for (int idx = tid; idx < 4096; idx += 256) {
        int rn = idx >> 3, o = idx & 7;
        int w = rn >> 2, tq = rn & 3;
        size_t J = (size_t)(b*1024 + m0 + w)*20 + t0 + tq;
        size_t ob = (((size_t)(1 + z)*JT_ + J) << 6) + ((o ^ (J & 7)) << 3);
        bf16 th[8], tl[8];
#pragma unroll
        for (int u = 0; u < 8; u++) {
            float vv = Dt[(tq*64 + o*8 + u)*129 + w];
            bf16 hv = __float2bfloat16(vv);
            th[u] = hv;
            tl[u] = __float2bfloat16(vv - bf2f(hv));
        }
        *(uint4*)(g_hch + ob) = *(uint4*)th;
        *(uint4*)(g_hcl + ob) = *(uint4*)tl;
    }
}

// ---------------- launch ----------------
extern "C" void kernel_launch(void* const* d_in, const int* in_sizes, int n_in,
                              void* d_out, int out_size) {
    const float* x    = (const float*)d_in[0];
    const float* tem  = (const float*)d_in[1];
    float* out = (float*)d_out;

    GemmArgs base = {};
    float *p_qkvJ, *p_bqkv, *p_bo, *p_bh, *p_b3u;
    cudaGetSymbolAddress((void**)&p_qkvJ, g_qkvJ);
    cudaGetSymbolAddress((void**)&p_bqkv, g_bqkv);
    cudaGetSymbolAddress((void**)&p_bo,   g_bo);
    cudaGetSymbolAddress((void**)&p_bh,   g_bh);
    cudaGetSymbolAddress((void**)&p_b3u,  g_b3u);
    bf16 *p_xeh, *p_xel, *p_atth, *p_attl, *p_hch, *p_hcl, *p_h01h, *p_h01l;
    bf16 *p_wqkvh, *p_wqkvl, *p_woh, *p_wol, *p_wgh, *p_wgl, *p_w3h, *p_w3l;
    cudaGetSymbolAddress((void**)&p_xeh, g_xeh);   cudaGetSymbolAddress((void**)&p_xel, g_xel);
    cudaGetSymbolAddress((void**)&p_atth, g_atth); cudaGetSymbolAddress((void**)&p_attl, g_attl);
    cudaGetSymbolAddress((void**)&p_hch, g_hch);   cudaGetSymbolAddress((void**)&p_hcl, g_hcl);
    cudaGetSymbolAddress((void**)&p_h01h, g_h01h); cudaGetSymbolAddress((void**)&p_h01l, g_h01l);
    cudaGetSymbolAddress((void**)&p_wqkvh, g_wqkvh); cudaGetSymbolAddress((void**)&p_wqkvl, g_wqkvl);
    cudaGetSymbolAddress((void**)&p_woh, g_woh);   cudaGetSymbolAddress((void**)&p_wol, g_wol);
    cudaGetSymbolAddress((void**)&p_wgh, g_wgh);   cudaGetSymbolAddress((void**)&p_wgl, g_wgl);
    cudaGetSymbolAddress((void**)&p_w3h, g_w3h);   cudaGetSymbolAddress((void**)&p_w3l, g_w3l);

    const int S192 = 1024 + 2*(32768 + 2*192*128) + 36864;
    const int S64  = 1024 + 2*(32768 + 2*64*128)  + 36864;
    const int S128 = 1024 + 2*(32768 + 2*128*128) + 36864;
    cudaFuncSetAttribute(k_gemm<128,192,0>, cudaFuncAttributeMaxDynamicSharedMemorySize, S192);
    cudaFuncSetAttribute(k_gemm<64,64,1>,   cudaFuncAttributeMaxDynamicSharedMemorySize, S64);
    cudaFuncSetAttribute(k_gemm<320,128,2>, cudaFuncAttributeMaxDynamicSharedMemorySize, S128);
    cudaFuncSetAttribute(k_gemm<128,192,3>, cudaFuncAttributeMaxDynamicSharedMemorySize, S192);
    cudaFuncSetAttribute(k_nconv_tc,        cudaFuncAttributeMaxDynamicSharedMemorySize, NSMEM);

    k_wsplit<<<370, 256>>>(
        (const float*)d_in[8],  (const float*)d_in[9],
        (const float*)d_in[10], (const float*)d_in[11],
        (const float*)d_in[12], (const float*)d_in[13],
        (const float*)d_in[14], (const float*)d_in[15],
        (const float*)d_in[16], (const float*)d_in[17],
        (const float*)d_in[18], (const float*)d_in[19],
        (const float*)d_in[20], (const float*)d_in[21],
        (const float*)d_in[22]);
    k_split_A<<<2048, 256>>>((const float*)d_in[2], (const float*)d_in[3],
                             (const float*)d_in[4], (const float*)d_in[5]);
    k_xe<<<4096, 256>>>(x, tem, (const float*)d_in[6], (const float*)d_in[7]);

    GemmArgs a = base;
    a.ah = p_xeh; a.al = p_xel; a.wh = p_wqkvh; a.wl = p_wqkvl;
    a.bias = p_bqkv; a.outf = p_qkvJ;
    k_gemm<128,192,0><<<GB_, 256, S192>>>(a);

    k_attn<<<16384, 256>>>();

    a = base;
    a.ah = p_atth; a.al = p_attl; a.wh = p_woh; a.wl = p_wol;
    a.bias = p_bo; a.oh = p_hch; a.ol = p_hcl;
    k_gemm<64,64,1><<<GB_, 256, S64>>>(a);

    k_xt<<<dim3(16, 20, 16), 256>>>();
    k_nconv_tc<<<dim3(80, 8, 4), 256, NSMEM>>>();

    a = base;
    a.ah = p_hch; a.al = p_hcl; a.wh = p_wgh; a.wl = p_wgl;
    a.bias = p_bh; a.oh = p_h01h; a.ol = p_h01l;
    k_gemm<320,128,2><<<GB_, 256, S128>>>(a);

    a = base;
    a.ah = p_h01h; a.al = p_h01l; a.wh = p_w3h; a.wl = p_w3l;
    a.bias = p_b3u; a.outfin = out;
    k_gemm<128,192,3><<<GB_, 256, S192>>>(a);
}